// round 13
// baseline (speedup 1.0000x reference)
#include <cuda_runtime.h>
#include <cuda_bf16.h>
#include <math.h>
#include <stdint.h>

// Problem constants
#define BATCH 8
#define NPTS  8192
#define DIM   256
#define DOUT  512
#define MPTS  2048
#define KNN   16
#define RTOT  (BATCH * NPTS)   // 65536 rows
#define EPS   1e-5f

// ---------------------------------------------------------------------------
// Scratch
// ---------------------------------------------------------------------------
__device__ __align__(128) float d_h1  [(size_t)RTOT * DIM];
__device__ __align__(128) float d_h2  [(size_t)RTOT * DIM];
__device__ __align__(128) float d_hpos[(size_t)RTOT * DIM];
__device__ __align__(128) float d_hgeo[(size_t)RTOT * DIM];
__device__ __align__(128) float d_q   [(size_t)RTOT * DIM];
__device__ __align__(128) float d_k   [(size_t)RTOT * DIM];
__device__ __align__(128) float d_v   [(size_t)RTOT * DIM];
__device__ __align__(128) float d_s   [(size_t)RTOT * DIM];
__device__ __align__(128) float d_pre [(size_t)RTOT * DIM];
__device__ __align__(128) float d_f   [(size_t)RTOT * DIM];
__device__ __align__(128) float d_g512[(size_t)RTOT * DOUT];
__device__ __align__(128) float d_wt  [14 * 256 * 256];

#define SLOT (256 * 256)

// ---------------------------------------------------------------------------
// helpers
// ---------------------------------------------------------------------------
__device__ __forceinline__ float f2tf32_rn(float v) {
    uint32_t u;
    asm("cvt.rna.tf32.f32 %0, %1;" : "=r"(u) : "f"(v));
    return __uint_as_float(u);
}

__device__ __forceinline__ void mma_tf32(float* c, const uint32_t* a, const uint32_t* b) {
    asm volatile(
        "mma.sync.aligned.m16n8k8.row.col.f32.tf32.tf32.f32 "
        "{%0,%1,%2,%3}, {%4,%5,%6,%7}, {%8,%9}, {%0,%1,%2,%3};"
        : "+f"(c[0]), "+f"(c[1]), "+f"(c[2]), "+f"(c[3])
        : "r"(a[0]), "r"(a[1]), "r"(a[2]), "r"(a[3]), "r"(b[0]), "r"(b[1]));
}

__device__ __forceinline__ uint32_t smem_u32(const void* p) {
    uint32_t a;
    asm("{ .reg .u64 t; cvta.to.shared.u64 t, %1; cvt.u32.u64 %0, t; }" : "=r"(a) : "l"(p));
    return a;
}

#define CP_ASYNC16(dst, src) \
    asm volatile("cp.async.cg.shared.global [%0], [%1], 16;" :: "r"(dst), "l"(src))
#define CP_COMMIT() asm volatile("cp.async.commit_group;")
template<int N> __device__ __forceinline__ void cp_wait() {
    asm volatile("cp.async.wait_group %0;" :: "n"(N));
}

#define LDSM_X4(r, addr) \
    asm volatile("ldmatrix.sync.aligned.m8n8.x4.shared.b16 {%0,%1,%2,%3}, [%4];" \
        : "=r"((r)[0]), "=r"((r)[1]), "=r"((r)[2]), "=r"((r)[3]) : "r"(addr))
#define LDSM_X2(r, addr) \
    asm volatile("ldmatrix.sync.aligned.m8n8.x2.shared.b16 {%0,%1}, [%2];" \
        : "=r"((r)[0]), "=r"((r)[1]) : "r"(addr))

// ---------------------------------------------------------------------------
// Batched weight transpose (rounded to tf32-rn at write)
// ---------------------------------------------------------------------------
__global__ __launch_bounds__(256) void transpose_all(
    const float* __restrict__ m1w2, const float* __restrict__ m2w2,
    const float* __restrict__ wq, const float* __restrict__ wk,
    const float* __restrict__ wv, const float* __restrict__ wo,
    const float* __restrict__ td, float* __restrict__ wt)
{
    __shared__ float t[32][33];
    const int z = blockIdx.z;
    const float* src;
    int srcN = 256, colOff = 0;
    float* dst;
    if (z < 12) {
        const int i = z / 6, j = z % 6;
        const size_t off = (size_t)i * SLOT;
        switch (j) {
            case 0: src = m1w2 + off; break;
            case 1: src = m2w2 + off; break;
            case 2: src = wq   + off; break;
            case 3: src = wk   + off; break;
            case 4: src = wv   + off; break;
            default: src = wo  + off; break;
        }
        dst = wt + (size_t)(i * 6 + j) * SLOT;
    } else {
        src = td; srcN = 512; colOff = (z - 12) * 256;
        dst = wt + (size_t)(12 + (z - 12)) * SLOT;
    }

    const int bx = blockIdx.x * 32;
    const int by = blockIdx.y * 32;
    const int tx = threadIdx.x & 31, ty = threadIdx.x >> 5;
#pragma unroll
    for (int i = ty; i < 32; i += 8)
        t[i][tx] = src[(size_t)(by + i) * srcN + colOff + bx + tx];
    __syncthreads();
#pragma unroll
    for (int i = ty; i < 32; i += 8)
        dst[(size_t)(bx + i) * 256 + by + tx] = f2tf32_rn(t[tx][i]);
}

// ---------------------------------------------------------------------------
// tf32 mma.sync GEMM, cp.async + ldmatrix.
// CTA tile 128x128, 256 threads (8 warps, 2x4), warp tile 64x32.
// K chunks of 32 floats, 3-stage ring (32KB/stage), 2 CTAs/SM.
// blockIdx.z==1 switches to job 2 (A2/W2/bias2/Cb, mode2, Nout2).
// modes: 0 = +bias[c]+Add[r,c]  1 = *scale  2 = none  3 = relu(bn(acc+bias))
//        4 = dual output: col<256 -> C (q, *scale), col>=256 -> C2 (k)
// ---------------------------------------------------------------------------
#define STG_BYTES 32768                 // A 16KB + B 16KB
#define TC_SMEM_TOTAL (3 * STG_BYTES)   // 96KB

__global__ void __launch_bounds__(256, 2) tc_gemm(
    const float* __restrict__ A, const float* __restrict__ Wt,
    const float* __restrict__ bias, const float* __restrict__ Add,
    float* __restrict__ C, float* __restrict__ C2,
    int Nout, int mode, float scale,
    const float* __restrict__ bn_g, const float* __restrict__ bn_b,
    const float* __restrict__ bn_mean, const float* __restrict__ bn_var,
    const float* __restrict__ A2, const float* __restrict__ W2,
    const float* __restrict__ bias2, float* __restrict__ Cb,
    int mode2, int Nout2)
{
    extern __shared__ char smem[];
    const uint32_t sbase = smem_u32(smem);
    const int tid  = threadIdx.x;
    const int lane = tid & 31;
    const int wid  = tid >> 5;
    const int wr   = wid >> 2;       // 0..1 -> 64-row slab
    const int wc   = wid & 3;        // 0..3 -> 32-col slab

    int mo = mode, No = Nout;
    if (blockIdx.z == 1) {           // second batched job
        A = A2; Wt = W2; bias = bias2; C = Cb;
        mo = mode2; No = Nout2;
        if ((int)blockIdx.x * 128 >= No) return;
    }

    const int blockRow = blockIdx.y * 128;
    const int blockCol = blockIdx.x * 128;

    const float* Abase = A  + (size_t)blockRow * 256;
    const float* Bbase = Wt + (size_t)blockCol * 256;

    // ---- cp.async loader: 4 16B per thread for A, 4 for B per chunk ----
    int rowL[4], qL[4];
    uint32_t offL[4];
#pragma unroll
    for (int i = 0; i < 4; i++) {
        const int idx = tid + i * 256;
        rowL[i] = idx >> 3;                 // 0..127
        qL[i]   = idx & 7;                  // 16B unit within row
        offL[i] = (uint32_t)rowL[i] * 128u + (uint32_t)((qL[i] ^ (rowL[i] & 7)) * 16);
    }

    auto issue_chunk = [&](int c, int s) {
        const int k0 = c * 32;
        const uint32_t ab = sbase + (uint32_t)s * STG_BYTES;
        const uint32_t bb = ab + 16384u;
#pragma unroll
        for (int i = 0; i < 4; i++)
            CP_ASYNC16(ab + offL[i], Abase + (size_t)rowL[i] * 256 + k0 + qL[i] * 4);
#pragma unroll
        for (int i = 0; i < 4; i++)
            CP_ASYNC16(bb + offL[i], Bbase + (size_t)rowL[i] * 256 + k0 + qL[i] * 4);
        CP_COMMIT();
    };

    // ---- ldmatrix addressing ----
    const int l7  = lane & 7;
    const int hA  = lane >> 4;
    const int hB  = (lane >> 3) & 1;
    uint32_t aOff[4], bOff[4];
#pragma unroll
    for (int t = 0; t < 4; t++) {
        const int rA = wr * 64 + t * 16 + ((lane >> 3) & 1) * 8 + l7;
        aOff[t] = (uint32_t)rA * 128u;
        const int rB = wc * 32 + t * 8 + l7;
        bOff[t] = (uint32_t)rB * 128u;
    }

    float acc[4][4][4];
#pragma unroll
    for (int i = 0; i < 4; i++)
#pragma unroll
        for (int j = 0; j < 4; j++)
#pragma unroll
            for (int e = 0; e < 4; e++) acc[i][j][e] = 0.f;

    auto compute = [&](int s) {
        const uint32_t sA = sbase + (uint32_t)s * STG_BYTES;
        const uint32_t sB = sA + 16384u;
#pragma unroll
        for (int kt = 0; kt < 4; kt++) {
            const uint32_t qa = (uint32_t)((((kt << 1) + hA) ^ l7) << 4);
            const uint32_t qb = (uint32_t)((((kt << 1) + hB) ^ l7) << 4);
            uint32_t aF[4][4], bF[4][2];
#pragma unroll
            for (int rt4 = 0; rt4 < 4; rt4++)
                LDSM_X4(aF[rt4], sA + aOff[rt4] + qa);
#pragma unroll
            for (int nt4 = 0; nt4 < 4; nt4++)
                LDSM_X2(bF[nt4], sB + bOff[nt4] + qb);
#pragma unroll
            for (int rt4 = 0; rt4 < 4; rt4++)
#pragma unroll
                for (int nt4 = 0; nt4 < 4; nt4++)
                    mma_tf32(acc[rt4][nt4], aF[rt4], bF[nt4]);
        }
    };

    issue_chunk(0, 0);
    issue_chunk(1, 1);
#pragma unroll
    for (int c = 0; c < 8; c++) {
        if (c == 7) cp_wait<0>(); else cp_wait<1>();
        __syncthreads();
        if (c + 2 < 8) issue_chunk(c + 2, (c + 2) % 3);
        compute(c % 3);
    }

    // epilogue
    const int g   = lane >> 2;
    const int tig = lane & 3;
#pragma unroll
    for (int rt4 = 0; rt4 < 4; rt4++) {
#pragma unroll
        for (int half = 0; half < 2; half++) {
            const int row = blockRow + wr * 64 + rt4 * 16 + g + half * 8;
            float* Crow = C + (size_t)row * No;
            const float* Arow = Add + (size_t)row * No;
#pragma unroll
            for (int nt4 = 0; nt4 < 4; nt4++) {
                const int col = blockCol + wc * 32 + nt4 * 8 + tig * 2;
                float v0 = acc[rt4][nt4][half * 2 + 0];
                float v1 = acc[rt4][nt4][half * 2 + 1];
                float2 out;
                if (mo == 0) {
                    out.x = v0 + bias[col]     + Arow[col];
                    out.y = v1 + bias[col + 1] + Arow[col + 1];
                    *(float2*)(Crow + col) = out;
                } else if (mo == 1) {
                    out.x = v0 * scale; out.y = v1 * scale;
                    *(float2*)(Crow + col) = out;
                } else if (mo == 2) {
                    out.x = v0; out.y = v1;
                    *(float2*)(Crow + col) = out;
                } else if (mo == 3) {
                    float t0 = (v0 + bias[col] - bn_mean[col]) *
                               rsqrtf(bn_var[col] + EPS) * bn_g[col] + bn_b[col];
                    float t1 = (v1 + bias[col + 1] - bn_mean[col + 1]) *
                               rsqrtf(bn_var[col + 1] + EPS) * bn_g[col + 1] + bn_b[col + 1];
                    out.x = fmaxf(t0, 0.f); out.y = fmaxf(t1, 0.f);
                    *(float2*)(Crow + col) = out;
                } else {  // mode 4: dual output q/k
                    if (col < 256) {
                        out.x = v0 * scale; out.y = v1 * scale;
                        *(float2*)(C + (size_t)row * 256 + col) = out;
                    } else {
                        out.x = v0; out.y = v1;
                        *(float2*)(C2 + (size_t)row * 256 + (col - 256)) = out;
                    }
                }
            }
        }
    }
}

// ---------------------------------------------------------------------------
// Per-chunk geometry + first MLP layers (4->256 and 6->256, relu)
// ---------------------------------------------------------------------------
__global__ __launch_bounds__(256) void geom_hidden_kernel(
    const float* __restrict__ pos,
    const float* __restrict__ w1, const float* __restrict__ b1,
    const float* __restrict__ w2, const float* __restrict__ b2,
    float* __restrict__ H1, float* __restrict__ H2, int cs)
{
    __shared__ float ps[64][3];
    __shared__ float lp[64][4];
    __shared__ float cog[3], avg[3];

    const int tid = threadIdx.x;
    const size_t gp = (size_t)blockIdx.x * cs;

    if (tid < cs) {
        ps[tid][0] = pos[(gp + tid) * 3 + 0];
        ps[tid][1] = pos[(gp + tid) * 3 + 1];
        ps[tid][2] = pos[(gp + tid) * 3 + 2];
    }
    __syncthreads();
    if (tid < 3) {
        float s = 0.f;
        for (int p = 0; p < cs; p++) s += ps[p][tid];
        cog[tid] = s / (float)cs;
    }
    __syncthreads();
    if (tid < cs) {
        float x = ps[tid][0] - cog[0];
        float y = ps[tid][1] - cog[1];
        float z = ps[tid][2] - cog[2];
        lp[tid][0] = x; lp[tid][1] = y; lp[tid][2] = z;
        lp[tid][3] = sqrtf(x * x + y * y + z * z);
    }
    __syncthreads();
    if (tid < 3) {
        float s = 0.f;
        for (int p = 0; p < cs; p++) s += lp[p][tid];
        avg[tid] = s / (float)cs;
    }
    __syncthreads();

    const int j = tid;
    float w1c[4], w2c[6];
#pragma unroll
    for (int t = 0; t < 4; t++) w1c[t] = w1[t * 256 + j];
#pragma unroll
    for (int t = 0; t < 6; t++) w2c[t] = w2[t * 256 + j];
    const float b1v = b1[j], b2v = b2[j];
    const float a0 = avg[0], a1 = avg[1], a2 = avg[2];

    for (int p = 0; p < cs; p++) {
        float x = lp[p][0], y = lp[p][1], z = lp[p][2], n = lp[p][3];
        float h1 = fmaxf(b1v + x * w1c[0] + y * w1c[1] + z * w1c[2] + n * w1c[3], 0.f);
        float h2 = fmaxf(b2v + a0 * w2c[0] + a1 * w2c[1] + a2 * w2c[2] +
                               x * w2c[3] + y * w2c[4] + z * w2c[5], 0.f);
        H1[(gp + p) * 256 + j] = f2tf32_rn(h1);
        H2[(gp + p) * 256 + j] = f2tf32_rn(h2);
    }
}

// ---------------------------------------------------------------------------
// Register-blocked chunk attention. CTA = 64 points.
// ---------------------------------------------------------------------------
#define SQ 257
#define SVP 264
#define ATTN_SMEM ((2 * 64 * SQ + 4096) * 4)

template<int CS>
__global__ __launch_bounds__(256) void attn_kernel(
    const float* __restrict__ Q, const float* __restrict__ Kf,
    const float* __restrict__ V, float* __restrict__ Out)
{
    extern __shared__ float sm[];
    float* Qs = sm;
    float* Ks = sm + 64 * SQ;
    float* P  = sm + 2 * 64 * SQ;
    float* Vs = sm;

    const int tid = threadIdx.x;
    const size_t base = (size_t)blockIdx.x * 64 * 256;

    for (int idx = tid; idx < 64 * 256; idx += 256) {
        int p = idx >> 8, t = idx & 255;
        Qs[p * SQ + t] = Q[base + idx];
        Ks[p * SQ + t] = Kf[base + idx];
    }
    __syncthreads();

    if (CS == 64) {
        const int i0 = (tid >> 4) * 4;
        const int j0 = (tid & 15) * 4;
        float acc[4][4] = {};
        for (int t = 0; t < 256; t++) {
            float qv[4], kv[4];
#pragma unroll
            for (int e = 0; e < 4; e++) qv[e] = Qs[(i0 + e) * SQ + t];
#pragma unroll
            for (int f = 0; f < 4; f++) kv[f] = Ks[(j0 + f) * SQ + t];
#pragma unroll
            for (int e = 0; e < 4; e++)
#pragma unroll
                for (int f = 0; f < 4; f++) acc[e][f] += qv[e] * kv[f];
        }
#pragma unroll
        for (int e = 0; e < 4; e++)
#pragma unroll
            for (int f = 0; f < 4; f++) P[(i0 + e) * 64 + j0 + f] = acc[e][f];
    } else {
        const int ch = tid >> 6;
        const int r  = (tid >> 2) & 15;
        const int j0 = (tid & 3) * 4;
        const int gi = ch * 16 + r;
        const int gj = ch * 16 + j0;
        float acc[4] = {};
        for (int t = 0; t < 256; t++) {
            float qv = Qs[gi * SQ + t];
#pragma unroll
            for (int f = 0; f < 4; f++) acc[f] += qv * Ks[(gj + f) * SQ + t];
        }
#pragma unroll
        for (int f = 0; f < 4; f++) P[ch * 256 + r * 16 + j0 + f] = acc[f];
    }
    __syncthreads();

    if (CS == 64) {
        const int warp = tid >> 5, lane = tid & 31;
        for (int i = warp; i < 64; i += 8) {
            float* row = P + i * 64;
            float a = row[lane], b = row[lane + 32];
            float mx = fmaxf(a, b);
#pragma unroll
            for (int o = 16; o; o >>= 1) mx = fmaxf(mx, __shfl_xor_sync(0xFFFFFFFFu, mx, o));
            float ea = __expf(a - mx), eb = __expf(b - mx);
            float sum = ea + eb;
#pragma unroll
            for (int o = 16; o; o >>= 1) sum += __shfl_xor_sync(0xFFFFFFFFu, sum, o);
            float inv = 1.f / sum;
            row[lane] = ea * inv;
            row[lane + 32] = eb * inv;
        }
    } else {
        if (tid < 64) {
            float* row = P + (tid >> 4) * 256 + (tid & 15) * 16;
            float mx = -1e30f;
#pragma unroll
            for (int j = 0; j < 16; j++) mx = fmaxf(mx, row[j]);
            float sum = 0.f;
            float e[16];
#pragma unroll
            for (int j = 0; j < 16; j++) { e[j] = __expf(row[j] - mx); sum += e[j]; }
            float inv = 1.f / sum;
#pragma unroll
            for (int j = 0; j < 16; j++) row[j] = e[j] * inv;
        }
    }
    __syncthreads();

    for (int idx = tid; idx < 64 * 256; idx += 256) {
        int p = idx >> 8, t = idx & 255;
        Vs[p * SVP + t] = V[base + idx];
    }
    __syncthreads();

    {
        const int i0 = (tid >> 4) * 4;
        const int tq = tid & 15;
        const int cb = i0 & ~(CS - 1);
        float acc[4][16] = {};
        for (int j = 0; j < CS; j++) {
            float pv[4];
            if (CS == 64) {
#pragma unroll
                for (int e = 0; e < 4; e++) pv[e] = P[(i0 + e) * 64 + j];
            } else {
                const int chk = i0 >> 4;
#pragma unroll
                for (int e = 0; e < 4; e++) pv[e] = P[chk * 256 + (i0 + e - cb) * 16 + j];
            }
            const float* vr = Vs + (cb + j) * SVP + tq;
            float vv[16];
#pragma unroll
            for (int m = 0; m < 16; m++) vv[m] = vr[m * 16];
#pragma unroll
            for (int e = 0; e < 4; e++)
#pragma unroll
                for (int m = 0; m < 16; m++) acc[e][m] += pv[e] * vv[m];
        }
#pragma unroll
        for (int e = 0; e < 4; e++)
#pragma unroll
            for (int m = 0; m < 16; m++)
                Out[base + (size_t)(i0 + e) * 256 + tq + m * 16] = f2tf32_rn(acc[e][m]);
    }
}

// ---------------------------------------------------------------------------
// LayerNorm over last dim (256): warp-per-row, 8 rows per CTA.
// ---------------------------------------------------------------------------
__global__ __launch_bounds__(256) void ln_kernel(
    const float* __restrict__ X, const float* __restrict__ g,
    const float* __restrict__ b, float* __restrict__ Y)
{
    const int warp = threadIdx.x >> 5, lane = threadIdx.x & 31;
    const size_t row = (size_t)blockIdx.x * 8 + warp;
    const float4* xr = (const float4*)(X + row * 256);
    float4 x0 = xr[lane], x1 = xr[lane + 32];

    float s = x0.x + x0.y + x0.z + x0.w + x1.x + x1.y + x1.z + x1.w;
#pragma unroll
    for (int o = 16; o; o >>= 1) s += __shfl_xor_sync(0xFFFFFFFFu, s, o);
    const float mu = s * (1.f / 256.f);

    float v = 0.f;
    float d0x = x0.x - mu, d0y = x0.y - mu, d0z = x0.z - mu, d0w = x0.w - mu;
    float d1x = x1.x - mu, d1y = x1.y - mu, d1z = x1.z - mu, d1w = x1.w - mu;
    v = d0x*d0x + d0y*d0y + d0z*d0z + d0w*d0w + d1x*d1x + d1y*d1y + d1z*d1z + d1w*d1w;
#pragma unroll
    for (int o = 16; o; o >>= 1) v += __shfl_xor_sync(0xFFFFFFFFu, v, o);
    const float inv = rsqrtf(v * (1.f / 256.f) + EPS);

    const float4 g0 = *(const float4*)&g[lane * 4];
    const float4 g1 = *(const float4*)&g[(lane + 32) * 4];
    const float4 b0 = *(const float4*)&b[lane * 4];
    const float4 b1 = *(const float4*)&b[(lane + 32) * 4];
    float4 y0, y1;
    y0.x = d0x * inv * g0.x + b0.x; y0.y = d0y * inv * g0.y + b0.y;
    y0.z = d0z * inv * g0.z + b0.z; y0.w = d0w * inv * g0.w + b0.w;
    y1.x = d1x * inv * g1.x + b1.x; y1.y = d1y * inv * g1.y + b1.y;
    y1.z = d1z * inv * g1.z + b1.z; y1.w = d1w * inv * g1.w + b1.w;
    float4* yr = (float4*)(Y + row * 256);
    yr[lane] = y0; yr[lane + 32] = y1;
}

// ---------------------------------------------------------------------------
// kNN gather + channel max (float4) + fused pos downsample
// ---------------------------------------------------------------------------
__global__ __launch_bounds__(128) void knn_max_kernel(
    const float* __restrict__ G, const int* __restrict__ knn,
    const float* __restrict__ pos, const int* __restrict__ fps,
    float* __restrict__ outPos, float* __restrict__ outFeat)
{
    const int bm = blockIdx.x;
    const int b  = bm / MPTS;
    const int tid = threadIdx.x;
    __shared__ int idxs[KNN];
    if (tid < KNN) idxs[tid] = knn[(size_t)bm * KNN + tid];
    if (tid >= 32 && tid < 35) {
        const int c = tid - 32;
        outPos[bm * 3 + c] = pos[((size_t)b * NPTS + fps[bm]) * 3 + c];
    }
    __syncthreads();
    float4 m = make_float4(-3.0e38f, -3.0e38f, -3.0e38f, -3.0e38f);
#pragma unroll
    for (int k = 0; k < KNN; k++) {
        const float4 gg = *(const float4*)&G[((size_t)b * NPTS + idxs[k]) * DOUT + tid * 4];
        m.x = fmaxf(m.x, gg.x); m.y = fmaxf(m.y, gg.y);
        m.z = fmaxf(m.z, gg.z); m.w = fmaxf(m.w, gg.w);
    }
    *(float4*)&outFeat[(size_t)bm * DOUT + tid * 4] = m;
}

// ---------------------------------------------------------------------------
// Orchestration
// ---------------------------------------------------------------------------
extern "C" void kernel_launch(void* const* d_in, const int* in_sizes, int n_in,
                              void* d_out, int out_size)
{
    const int s = (n_in >= 27) ? 6 : 4;

    const float* pos     = (const float*)d_in[0];
    const float* feat    = (const float*)d_in[1];
    const int*   fps     = (const int*)  d_in[2];
    const int*   knn     = (const int*)  d_in[3];
    const float* mlp1_w1 = (const float*)d_in[s + 0];
    const float* mlp1_b1 = (const float*)d_in[s + 1];
    const float* mlp1_w2 = (const float*)d_in[s + 2];
    const float* mlp1_b2 = (const float*)d_in[s + 3];
    const float* mlp2_w1 = (const float*)d_in[s + 4];
    const float* mlp2_b1 = (const float*)d_in[s + 5];
    const float* mlp2_w2 = (const float*)d_in[s + 6];
    const float* mlp2_b2 = (const float*)d_in[s + 7];
    const float* wq      = (const float*)d_in[s + 8];
    const float* wk      = (const float*)d_in[s + 9];
    const float* wv      = (const float*)d_in[s + 10];
    const float* wo      = (const float*)d_in[s + 11];
    const float* bo      = (const float*)d_in[s + 12];
    const float* ln_g    = (const float*)d_in[s + 13];
    const float* ln_b    = (const float*)d_in[s + 14];
    const float* td_w    = (const float*)d_in[s + 15];
    const float* td_b    = (const float*)d_in[s + 16];
    const float* bn_g    = (const float*)d_in[s + 17];
    const float* bn_b    = (const float*)d_in[s + 18];
    const float* bn_mean = (const float*)d_in[s + 19];
    const float* bn_var  = (const float*)d_in[s + 20];

    float *h1, *h2, *hpos, *hgeo, *qb, *kb, *vb, *sb, *pre, *fb, *g512, *wt;
    cudaGetSymbolAddress((void**)&h1,   d_h1);
    cudaGetSymbolAddress((void**)&h2,   d_h2);
    cudaGetSymbolAddress((void**)&hpos, d_hpos);
    cudaGetSymbolAddress((void**)&hgeo, d_hgeo);
    cudaGetSymbolAddress((void**)&qb,   d_q);
    cudaGetSymbolAddress((void**)&kb,   d_k);
    cudaGetSymbolAddress((void**)&vb,   d_v);
    cudaGetSymbolAddress((void**)&sb,   d_s);
    cudaGetSymbolAddress((void**)&pre,  d_pre);
    cudaGetSymbolAddress((void**)&fb,   d_f);
    cudaGetSymbolAddress((void**)&g512, d_g512);
    cudaGetSymbolAddress((void**)&wt,   d_wt);

    cudaFuncSetAttribute(tc_gemm,
                         cudaFuncAttributeMaxDynamicSharedMemorySize, TC_SMEM_TOTAL);
    cudaFuncSetAttribute(attn_kernel<16>,
                         cudaFuncAttributeMaxDynamicSharedMemorySize, ATTN_SMEM);
    cudaFuncSetAttribute(attn_kernel<64>,
                         cudaFuncAttributeMaxDynamicSharedMemorySize, ATTN_SMEM);

    transpose_all<<<dim3(8, 8, 14), 256>>>(mlp1_w2, mlp2_w2, wq, wk, wv, wo, td_w, wt);

    const dim3 gemmBlk(256);
    const dim3 grid256x2(2, RTOT / 128, 2);  // batched hpos+hgeo
    const dim3 gridQKV(4, RTOT / 128, 2);    // batched qk(512) + v(256)
    const dim3 grid256(2, RTOT / 128, 1);
    const dim3 grid512(4, RTOT / 128, 1);

    for (int blk = 0; blk < 2; blk++) {
        const int cs = (blk == 0) ? 16 : 64;
        const int i  = blk;
        const float* fin = (blk == 0) ? feat : fb;
        const size_t bOff = (size_t)i * 256;
        float* Wt0 = wt + (size_t)(i * 6) * SLOT;

        geom_hidden_kernel<<<RTOT / cs, 256>>>(
            pos, mlp1_w1 + (size_t)i * 4 * 256, mlp1_b1 + bOff,
            mlp2_w1 + (size_t)i * 6 * 256, mlp2_b1 + bOff, h1, h2, cs);

        // batched: z=0: hpos = h1@W0 + b + fin ; z=1: hgeo = h2@W1 + b + fin
        tc_gemm<<<grid256x2, gemmBlk, TC_SMEM_TOTAL>>>(h1, Wt0 + 0 * SLOT, mlp1_b2 + bOff, fin,
            hpos, nullptr, DIM, 0, 1.f, nullptr, nullptr, nullptr, nullptr,
            h2, Wt0 + 1 * SLOT, mlp2_b2 + bOff, hgeo, 0, DIM);

        // batched: z=0: q|k = hgeo@[wq|wk] (mode 4, 512) ; z=1: v = hpos@wv (mode 2, 256)
        tc_gemm<<<gridQKV, gemmBlk, TC_SMEM_TOTAL>>>(hgeo, Wt0 + 2 * SLOT, nullptr, feat,
            qb, kb, DOUT, 4, 1.f / 16.f, nullptr, nullptr, nullptr, nullptr,
            hpos, Wt0 + 4 * SLOT, nullptr, vb, 2, DIM);

        if (cs == 16)
            attn_kernel<16><<<RTOT / 64, 256, ATTN_SMEM>>>(qb, kb, vb, sb);
        else
            attn_kernel<64><<<RTOT / 64, 256, ATTN_SMEM>>>(qb, kb, vb, sb);

        // pre = hpos + attn@wo + bo
        tc_gemm<<<grid256, gemmBlk, TC_SMEM_TOTAL>>>(sb, Wt0 + 5 * SLOT, bo + bOff, hpos,
            pre, nullptr, DIM, 0, 1.f, nullptr, nullptr, nullptr, nullptr,
            nullptr, nullptr, nullptr, nullptr, 0, DIM);

        ln_kernel<<<RTOT / 8, 256>>>(pre, ln_g + bOff, ln_b + bOff, fb);
    }

    tc_gemm<<<grid512, gemmBlk, TC_SMEM_TOTAL>>>(fb, wt + 12 * SLOT, td_b, feat,
        g512, nullptr, DOUT, 3, 1.f, bn_g, bn_b, bn_mean, bn_var,
        nullptr, nullptr, nullptr, nullptr, 0, DIM);

    float* outp = (float*)d_out;
    knn_max_kernel<<<BATCH * MPTS, 128>>>(g512, knn, pos, fps,
                                          outp, outp + BATCH * MPTS * 3);
}

// round 14
// speedup vs baseline: 1.0967x; 1.0967x over previous
#include <cuda_runtime.h>
#include <cuda_bf16.h>
#include <math.h>
#include <stdint.h>

// Problem constants
#define BATCH 8
#define NPTS  8192
#define DIM   256
#define DOUT  512
#define MPTS  2048
#define KNN   16
#define RTOT  (BATCH * NPTS)   // 65536 rows
#define EPS   1e-5f

// ---------------------------------------------------------------------------
// Scratch
// ---------------------------------------------------------------------------
__device__ __align__(128) float d_h1  [(size_t)RTOT * DIM];
__device__ __align__(128) float d_h2  [(size_t)RTOT * DIM];
__device__ __align__(128) float d_hpos[(size_t)RTOT * DIM];
__device__ __align__(128) float d_hgeo[(size_t)RTOT * DIM];
__device__ __align__(128) float d_q   [(size_t)RTOT * DIM];
__device__ __align__(128) float d_k   [(size_t)RTOT * DIM];
__device__ __align__(128) float d_v   [(size_t)RTOT * DIM];
__device__ __align__(128) float d_s   [(size_t)RTOT * DIM];
__device__ __align__(128) float d_pre [(size_t)RTOT * DIM];
__device__ __align__(128) float d_f   [(size_t)RTOT * DIM];
__device__ __align__(128) float d_g512[(size_t)RTOT * DOUT];
__device__ __align__(128) float d_wt  [14 * 256 * 256];

#define SLOT (256 * 256)

// ---------------------------------------------------------------------------
// helpers
// ---------------------------------------------------------------------------
__device__ __forceinline__ float f2tf32_rn(float v) {
    uint32_t u;
    asm("cvt.rna.tf32.f32 %0, %1;" : "=r"(u) : "f"(v));
    return __uint_as_float(u);
}

__device__ __forceinline__ void mma_tf32(float* c, const uint32_t* a, const uint32_t* b) {
    asm volatile(
        "mma.sync.aligned.m16n8k8.row.col.f32.tf32.tf32.f32 "
        "{%0,%1,%2,%3}, {%4,%5,%6,%7}, {%8,%9}, {%0,%1,%2,%3};"
        : "+f"(c[0]), "+f"(c[1]), "+f"(c[2]), "+f"(c[3])
        : "r"(a[0]), "r"(a[1]), "r"(a[2]), "r"(a[3]), "r"(b[0]), "r"(b[1]));
}

__device__ __forceinline__ uint32_t smem_u32(const void* p) {
    uint32_t a;
    asm("{ .reg .u64 t; cvta.to.shared.u64 t, %1; cvt.u32.u64 %0, t; }" : "=r"(a) : "l"(p));
    return a;
}

#define CP_ASYNC16(dst, src) \
    asm volatile("cp.async.cg.shared.global [%0], [%1], 16;" :: "r"(dst), "l"(src))
#define CP_COMMIT() asm volatile("cp.async.commit_group;")
template<int N> __device__ __forceinline__ void cp_wait() {
    asm volatile("cp.async.wait_group %0;" :: "n"(N));
}

#define LDSM_X4(r, addr) \
    asm volatile("ldmatrix.sync.aligned.m8n8.x4.shared.b16 {%0,%1,%2,%3}, [%4];" \
        : "=r"((r)[0]), "=r"((r)[1]), "=r"((r)[2]), "=r"((r)[3]) : "r"(addr))
#define LDSM_X2(r, addr) \
    asm volatile("ldmatrix.sync.aligned.m8n8.x2.shared.b16 {%0,%1}, [%2];" \
        : "=r"((r)[0]), "=r"((r)[1]) : "r"(addr))

// ---------------------------------------------------------------------------
// Batched weight transpose (rounded to tf32-rn at write)
// ---------------------------------------------------------------------------
__global__ __launch_bounds__(256) void transpose_all(
    const float* __restrict__ m1w2, const float* __restrict__ m2w2,
    const float* __restrict__ wq, const float* __restrict__ wk,
    const float* __restrict__ wv, const float* __restrict__ wo,
    const float* __restrict__ td, float* __restrict__ wt)
{
    __shared__ float t[32][33];
    const int z = blockIdx.z;
    const float* src;
    int srcN = 256, colOff = 0;
    float* dst;
    if (z < 12) {
        const int i = z / 6, j = z % 6;
        const size_t off = (size_t)i * SLOT;
        switch (j) {
            case 0: src = m1w2 + off; break;
            case 1: src = m2w2 + off; break;
            case 2: src = wq   + off; break;
            case 3: src = wk   + off; break;
            case 4: src = wv   + off; break;
            default: src = wo  + off; break;
        }
        dst = wt + (size_t)(i * 6 + j) * SLOT;
    } else {
        src = td; srcN = 512; colOff = (z - 12) * 256;
        dst = wt + (size_t)(12 + (z - 12)) * SLOT;
    }

    const int bx = blockIdx.x * 32;
    const int by = blockIdx.y * 32;
    const int tx = threadIdx.x & 31, ty = threadIdx.x >> 5;
#pragma unroll
    for (int i = ty; i < 32; i += 8)
        t[i][tx] = src[(size_t)(by + i) * srcN + colOff + bx + tx];
    __syncthreads();
#pragma unroll
    for (int i = ty; i < 32; i += 8)
        dst[(size_t)(bx + i) * 256 + by + tx] = f2tf32_rn(t[tx][i]);
}

// ---------------------------------------------------------------------------
// tf32 mma.sync GEMM, cp.async + ldmatrix.
// CTA tile 128x128, 256 threads (8 warps, 2x4), warp tile 64x32.
// K chunks of 32 floats, 3-stage ring (32KB/stage), 2 CTAs/SM.
// blockIdx.z==1 switches to job 2 (A2/W2/bias2/Cb), same mode/Nout.
// modes: 0 = +bias[c]+Add[r,c]  1 = *scale  2 = none  3 = relu(bn(acc+bias))
//        4 = dual output: col<256 -> C (q, *scale), col>=256 -> C2 (k)
// ---------------------------------------------------------------------------
#define STG_BYTES 32768                 // A 16KB + B 16KB
#define TC_SMEM_TOTAL (3 * STG_BYTES)   // 96KB

__global__ void __launch_bounds__(256, 2) tc_gemm(
    const float* __restrict__ A, const float* __restrict__ Wt,
    const float* __restrict__ bias, const float* __restrict__ Add,
    float* __restrict__ C, float* __restrict__ C2,
    int Nout, int mode, float scale,
    const float* __restrict__ bn_g, const float* __restrict__ bn_b,
    const float* __restrict__ bn_mean, const float* __restrict__ bn_var,
    const float* __restrict__ A2, const float* __restrict__ W2,
    const float* __restrict__ bias2, float* __restrict__ Cb)
{
    extern __shared__ char smem[];
    const uint32_t sbase = smem_u32(smem);
    const int tid  = threadIdx.x;
    const int lane = tid & 31;
    const int wid  = tid >> 5;
    const int wr   = wid >> 2;       // 0..1 -> 64-row slab
    const int wc   = wid & 3;        // 0..3 -> 32-col slab

    if (blockIdx.z == 1) {           // second batched job
        A = A2; Wt = W2; bias = bias2; C = Cb;
    }

    const int blockRow = blockIdx.y * 128;
    const int blockCol = blockIdx.x * 128;

    const float* Abase = A  + (size_t)blockRow * 256;
    const float* Bbase = Wt + (size_t)blockCol * 256;

    // ---- cp.async loader: 4 16B per thread for A, 4 for B per chunk ----
    int rowL[4], qL[4];
    uint32_t offL[4];
#pragma unroll
    for (int i = 0; i < 4; i++) {
        const int idx = tid + i * 256;
        rowL[i] = idx >> 3;                 // 0..127
        qL[i]   = idx & 7;                  // 16B unit within row
        offL[i] = (uint32_t)rowL[i] * 128u + (uint32_t)((qL[i] ^ (rowL[i] & 7)) * 16);
    }

    auto issue_chunk = [&](int c, int s) {
        const int k0 = c * 32;
        const uint32_t ab = sbase + (uint32_t)s * STG_BYTES;
        const uint32_t bb = ab + 16384u;
#pragma unroll
        for (int i = 0; i < 4; i++)
            CP_ASYNC16(ab + offL[i], Abase + (size_t)rowL[i] * 256 + k0 + qL[i] * 4);
#pragma unroll
        for (int i = 0; i < 4; i++)
            CP_ASYNC16(bb + offL[i], Bbase + (size_t)rowL[i] * 256 + k0 + qL[i] * 4);
        CP_COMMIT();
    };

    // ---- ldmatrix addressing ----
    const int l7  = lane & 7;
    const int hA  = lane >> 4;
    const int hB  = (lane >> 3) & 1;
    uint32_t aOff[4], bOff[4];
#pragma unroll
    for (int t = 0; t < 4; t++) {
        const int rA = wr * 64 + t * 16 + ((lane >> 3) & 1) * 8 + l7;
        aOff[t] = (uint32_t)rA * 128u;
        const int rB = wc * 32 + t * 8 + l7;
        bOff[t] = (uint32_t)rB * 128u;
    }

    float acc[4][4][4];
#pragma unroll
    for (int i = 0; i < 4; i++)
#pragma unroll
        for (int j = 0; j < 4; j++)
#pragma unroll
            for (int e = 0; e < 4; e++) acc[i][j][e] = 0.f;

    auto compute = [&](int s) {
        const uint32_t sA = sbase + (uint32_t)s * STG_BYTES;
        const uint32_t sB = sA + 16384u;
#pragma unroll
        for (int kt = 0; kt < 4; kt++) {
            const uint32_t qa = (uint32_t)((((kt << 1) + hA) ^ l7) << 4);
            const uint32_t qb = (uint32_t)((((kt << 1) + hB) ^ l7) << 4);
            uint32_t aF[4][4], bF[4][2];
#pragma unroll
            for (int rt4 = 0; rt4 < 4; rt4++)
                LDSM_X4(aF[rt4], sA + aOff[rt4] + qa);
#pragma unroll
            for (int nt4 = 0; nt4 < 4; nt4++)
                LDSM_X2(bF[nt4], sB + bOff[nt4] + qb);
#pragma unroll
            for (int rt4 = 0; rt4 < 4; rt4++)
#pragma unroll
                for (int nt4 = 0; nt4 < 4; nt4++)
                    mma_tf32(acc[rt4][nt4], aF[rt4], bF[nt4]);
        }
    };

    issue_chunk(0, 0);
    issue_chunk(1, 1);
#pragma unroll
    for (int c = 0; c < 8; c++) {
        if (c == 7) cp_wait<0>(); else cp_wait<1>();
        __syncthreads();
        if (c + 2 < 8) issue_chunk(c + 2, (c + 2) % 3);
        compute(c % 3);
    }

    // epilogue
    const int g   = lane >> 2;
    const int tig = lane & 3;
#pragma unroll
    for (int rt4 = 0; rt4 < 4; rt4++) {
#pragma unroll
        for (int half = 0; half < 2; half++) {
            const int row = blockRow + wr * 64 + rt4 * 16 + g + half * 8;
            float* Crow = C + (size_t)row * Nout;
            const float* Arow = Add + (size_t)row * Nout;
#pragma unroll
            for (int nt4 = 0; nt4 < 4; nt4++) {
                const int col = blockCol + wc * 32 + nt4 * 8 + tig * 2;
                float v0 = acc[rt4][nt4][half * 2 + 0];
                float v1 = acc[rt4][nt4][half * 2 + 1];
                float2 out;
                if (mode == 0) {
                    out.x = v0 + bias[col]     + Arow[col];
                    out.y = v1 + bias[col + 1] + Arow[col + 1];
                    *(float2*)(Crow + col) = out;
                } else if (mode == 1) {
                    out.x = v0 * scale; out.y = v1 * scale;
                    *(float2*)(Crow + col) = out;
                } else if (mode == 2) {
                    out.x = v0; out.y = v1;
                    *(float2*)(Crow + col) = out;
                } else if (mode == 3) {
                    float t0 = (v0 + bias[col] - bn_mean[col]) *
                               rsqrtf(bn_var[col] + EPS) * bn_g[col] + bn_b[col];
                    float t1 = (v1 + bias[col + 1] - bn_mean[col + 1]) *
                               rsqrtf(bn_var[col + 1] + EPS) * bn_g[col + 1] + bn_b[col + 1];
                    out.x = fmaxf(t0, 0.f); out.y = fmaxf(t1, 0.f);
                    *(float2*)(Crow + col) = out;
                } else {  // mode 4: dual output q/k
                    if (col < 256) {
                        out.x = v0 * scale; out.y = v1 * scale;
                        *(float2*)(C + (size_t)row * 256 + col) = out;
                    } else {
                        out.x = v0; out.y = v1;
                        *(float2*)(C2 + (size_t)row * 256 + (col - 256)) = out;
                    }
                }
            }
        }
    }
}

// ---------------------------------------------------------------------------
// Per-chunk geometry + first MLP layers (4->256 and 6->256, relu)
// ---------------------------------------------------------------------------
__global__ __launch_bounds__(256) void geom_hidden_kernel(
    const float* __restrict__ pos,
    const float* __restrict__ w1, const float* __restrict__ b1,
    const float* __restrict__ w2, const float* __restrict__ b2,
    float* __restrict__ H1, float* __restrict__ H2, int cs)
{
    __shared__ float ps[64][3];
    __shared__ float lp[64][4];
    __shared__ float cog[3], avg[3];

    const int tid = threadIdx.x;
    const size_t gp = (size_t)blockIdx.x * cs;

    if (tid < cs) {
        ps[tid][0] = pos[(gp + tid) * 3 + 0];
        ps[tid][1] = pos[(gp + tid) * 3 + 1];
        ps[tid][2] = pos[(gp + tid) * 3 + 2];
    }
    __syncthreads();
    if (tid < 3) {
        float s = 0.f;
        for (int p = 0; p < cs; p++) s += ps[p][tid];
        cog[tid] = s / (float)cs;
    }
    __syncthreads();
    if (tid < cs) {
        float x = ps[tid][0] - cog[0];
        float y = ps[tid][1] - cog[1];
        float z = ps[tid][2] - cog[2];
        lp[tid][0] = x; lp[tid][1] = y; lp[tid][2] = z;
        lp[tid][3] = sqrtf(x * x + y * y + z * z);
    }
    __syncthreads();
    if (tid < 3) {
        float s = 0.f;
        for (int p = 0; p < cs; p++) s += lp[p][tid];
        avg[tid] = s / (float)cs;
    }
    __syncthreads();

    const int j = tid;
    float w1c[4], w2c[6];
#pragma unroll
    for (int t = 0; t < 4; t++) w1c[t] = w1[t * 256 + j];
#pragma unroll
    for (int t = 0; t < 6; t++) w2c[t] = w2[t * 256 + j];
    const float b1v = b1[j], b2v = b2[j];
    const float a0 = avg[0], a1 = avg[1], a2 = avg[2];

    for (int p = 0; p < cs; p++) {
        float x = lp[p][0], y = lp[p][1], z = lp[p][2], n = lp[p][3];
        float h1 = fmaxf(b1v + x * w1c[0] + y * w1c[1] + z * w1c[2] + n * w1c[3], 0.f);
        float h2 = fmaxf(b2v + a0 * w2c[0] + a1 * w2c[1] + a2 * w2c[2] +
                               x * w2c[3] + y * w2c[4] + z * w2c[5], 0.f);
        H1[(gp + p) * 256 + j] = f2tf32_rn(h1);
        H2[(gp + p) * 256 + j] = f2tf32_rn(h2);
    }
}

// ---------------------------------------------------------------------------
// Register-blocked chunk attention. CTA = 64 points.
// ---------------------------------------------------------------------------
#define SQ 257
#define SVP 264
#define ATTN_SMEM ((2 * 64 * SQ + 4096) * 4)

template<int CS>
__global__ __launch_bounds__(256) void attn_kernel(
    const float* __restrict__ Q, const float* __restrict__ Kf,
    const float* __restrict__ V, float* __restrict__ Out)
{
    extern __shared__ float sm[];
    float* Qs = sm;
    float* Ks = sm + 64 * SQ;
    float* P  = sm + 2 * 64 * SQ;
    float* Vs = sm;

    const int tid = threadIdx.x;
    const size_t base = (size_t)blockIdx.x * 64 * 256;

    for (int idx = tid; idx < 64 * 256; idx += 256) {
        int p = idx >> 8, t = idx & 255;
        Qs[p * SQ + t] = Q[base + idx];
        Ks[p * SQ + t] = Kf[base + idx];
    }
    __syncthreads();

    if (CS == 64) {
        const int i0 = (tid >> 4) * 4;
        const int j0 = (tid & 15) * 4;
        float acc[4][4] = {};
        for (int t = 0; t < 256; t++) {
            float qv[4], kv[4];
#pragma unroll
            for (int e = 0; e < 4; e++) qv[e] = Qs[(i0 + e) * SQ + t];
#pragma unroll
            for (int f = 0; f < 4; f++) kv[f] = Ks[(j0 + f) * SQ + t];
#pragma unroll
            for (int e = 0; e < 4; e++)
#pragma unroll
                for (int f = 0; f < 4; f++) acc[e][f] += qv[e] * kv[f];
        }
#pragma unroll
        for (int e = 0; e < 4; e++)
#pragma unroll
            for (int f = 0; f < 4; f++) P[(i0 + e) * 64 + j0 + f] = acc[e][f];
    } else {
        const int ch = tid >> 6;
        const int r  = (tid >> 2) & 15;
        const int j0 = (tid & 3) * 4;
        const int gi = ch * 16 + r;
        const int gj = ch * 16 + j0;
        float acc[4] = {};
        for (int t = 0; t < 256; t++) {
            float qv = Qs[gi * SQ + t];
#pragma unroll
            for (int f = 0; f < 4; f++) acc[f] += qv * Ks[(gj + f) * SQ + t];
        }
#pragma unroll
        for (int f = 0; f < 4; f++) P[ch * 256 + r * 16 + j0 + f] = acc[f];
    }
    __syncthreads();

    if (CS == 64) {
        const int warp = tid >> 5, lane = tid & 31;
        for (int i = warp; i < 64; i += 8) {
            float* row = P + i * 64;
            float a = row[lane], b = row[lane + 32];
            float mx = fmaxf(a, b);
#pragma unroll
            for (int o = 16; o; o >>= 1) mx = fmaxf(mx, __shfl_xor_sync(0xFFFFFFFFu, mx, o));
            float ea = __expf(a - mx), eb = __expf(b - mx);
            float sum = ea + eb;
#pragma unroll
            for (int o = 16; o; o >>= 1) sum += __shfl_xor_sync(0xFFFFFFFFu, sum, o);
            float inv = 1.f / sum;
            row[lane] = ea * inv;
            row[lane + 32] = eb * inv;
        }
    } else {
        if (tid < 64) {
            float* row = P + (tid >> 4) * 256 + (tid & 15) * 16;
            float mx = -1e30f;
#pragma unroll
            for (int j = 0; j < 16; j++) mx = fmaxf(mx, row[j]);
            float sum = 0.f;
            float e[16];
#pragma unroll
            for (int j = 0; j < 16; j++) { e[j] = __expf(row[j] - mx); sum += e[j]; }
            float inv = 1.f / sum;
#pragma unroll
            for (int j = 0; j < 16; j++) row[j] = e[j] * inv;
        }
    }
    __syncthreads();

    for (int idx = tid; idx < 64 * 256; idx += 256) {
        int p = idx >> 8, t = idx & 255;
        Vs[p * SVP + t] = V[base + idx];
    }
    __syncthreads();

    {
        const int i0 = (tid >> 4) * 4;
        const int tq = tid & 15;
        const int cb = i0 & ~(CS - 1);
        float acc[4][16] = {};
        for (int j = 0; j < CS; j++) {
            float pv[4];
            if (CS == 64) {
#pragma unroll
                for (int e = 0; e < 4; e++) pv[e] = P[(i0 + e) * 64 + j];
            } else {
                const int chk = i0 >> 4;
#pragma unroll
                for (int e = 0; e < 4; e++) pv[e] = P[chk * 256 + (i0 + e - cb) * 16 + j];
            }
            const float* vr = Vs + (cb + j) * SVP + tq;
            float vv[16];
#pragma unroll
            for (int m = 0; m < 16; m++) vv[m] = vr[m * 16];
#pragma unroll
            for (int e = 0; e < 4; e++)
#pragma unroll
                for (int m = 0; m < 16; m++) acc[e][m] += pv[e] * vv[m];
        }
#pragma unroll
        for (int e = 0; e < 4; e++)
#pragma unroll
            for (int m = 0; m < 16; m++)
                Out[base + (size_t)(i0 + e) * 256 + tq + m * 16] = f2tf32_rn(acc[e][m]);
    }
}

// ---------------------------------------------------------------------------
// LayerNorm over last dim (256): warp-per-row, 8 rows per CTA.
// ---------------------------------------------------------------------------
__global__ __launch_bounds__(256) void ln_kernel(
    const float* __restrict__ X, const float* __restrict__ g,
    const float* __restrict__ b, float* __restrict__ Y)
{
    const int warp = threadIdx.x >> 5, lane = threadIdx.x & 31;
    const size_t row = (size_t)blockIdx.x * 8 + warp;
    const float4* xr = (const float4*)(X + row * 256);
    float4 x0 = xr[lane], x1 = xr[lane + 32];

    float s = x0.x + x0.y + x0.z + x0.w + x1.x + x1.y + x1.z + x1.w;
#pragma unroll
    for (int o = 16; o; o >>= 1) s += __shfl_xor_sync(0xFFFFFFFFu, s, o);
    const float mu = s * (1.f / 256.f);

    float v = 0.f;
    float d0x = x0.x - mu, d0y = x0.y - mu, d0z = x0.z - mu, d0w = x0.w - mu;
    float d1x = x1.x - mu, d1y = x1.y - mu, d1z = x1.z - mu, d1w = x1.w - mu;
    v = d0x*d0x + d0y*d0y + d0z*d0z + d0w*d0w + d1x*d1x + d1y*d1y + d1z*d1z + d1w*d1w;
#pragma unroll
    for (int o = 16; o; o >>= 1) v += __shfl_xor_sync(0xFFFFFFFFu, v, o);
    const float inv = rsqrtf(v * (1.f / 256.f) + EPS);

    const float4 g0 = *(const float4*)&g[lane * 4];
    const float4 g1 = *(const float4*)&g[(lane + 32) * 4];
    const float4 b0 = *(const float4*)&b[lane * 4];
    const float4 b1 = *(const float4*)&b[(lane + 32) * 4];
    float4 y0, y1;
    y0.x = d0x * inv * g0.x + b0.x; y0.y = d0y * inv * g0.y + b0.y;
    y0.z = d0z * inv * g0.z + b0.z; y0.w = d0w * inv * g0.w + b0.w;
    y1.x = d1x * inv * g1.x + b1.x; y1.y = d1y * inv * g1.y + b1.y;
    y1.z = d1z * inv * g1.z + b1.z; y1.w = d1w * inv * g1.w + b1.w;
    float4* yr = (float4*)(Y + row * 256);
    yr[lane] = y0; yr[lane + 32] = y1;
}

// ---------------------------------------------------------------------------
// kNN gather + channel max (float4) + fused pos downsample
// ---------------------------------------------------------------------------
__global__ __launch_bounds__(128) void knn_max_kernel(
    const float* __restrict__ G, const int* __restrict__ knn,
    const float* __restrict__ pos, const int* __restrict__ fps,
    float* __restrict__ outPos, float* __restrict__ outFeat)
{
    const int bm = blockIdx.x;
    const int b  = bm / MPTS;
    const int tid = threadIdx.x;
    __shared__ int idxs[KNN];
    if (tid < KNN) idxs[tid] = knn[(size_t)bm * KNN + tid];
    if (tid >= 32 && tid < 35) {
        const int c = tid - 32;
        outPos[bm * 3 + c] = pos[((size_t)b * NPTS + fps[bm]) * 3 + c];
    }
    __syncthreads();
    float4 m = make_float4(-3.0e38f, -3.0e38f, -3.0e38f, -3.0e38f);
#pragma unroll
    for (int k = 0; k < KNN; k++) {
        const float4 gg = *(const float4*)&G[((size_t)b * NPTS + idxs[k]) * DOUT + tid * 4];
        m.x = fmaxf(m.x, gg.x); m.y = fmaxf(m.y, gg.y);
        m.z = fmaxf(m.z, gg.z); m.w = fmaxf(m.w, gg.w);
    }
    *(float4*)&outFeat[(size_t)bm * DOUT + tid * 4] = m;
}

// ---------------------------------------------------------------------------
// Orchestration
// ---------------------------------------------------------------------------
extern "C" void kernel_launch(void* const* d_in, const int* in_sizes, int n_in,
                              void* d_out, int out_size)
{
    const int s = (n_in >= 27) ? 6 : 4;

    const float* pos     = (const float*)d_in[0];
    const float* feat    = (const float*)d_in[1];
    const int*   fps     = (const int*)  d_in[2];
    const int*   knn     = (const int*)  d_in[3];
    const float* mlp1_w1 = (const float*)d_in[s + 0];
    const float* mlp1_b1 = (const float*)d_in[s + 1];
    const float* mlp1_w2 = (const float*)d_in[s + 2];
    const float* mlp1_b2 = (const float*)d_in[s + 3];
    const float* mlp2_w1 = (const float*)d_in[s + 4];
    const float* mlp2_b1 = (const float*)d_in[s + 5];
    const float* mlp2_w2 = (const float*)d_in[s + 6];
    const float* mlp2_b2 = (const float*)d_in[s + 7];
    const float* wq      = (const float*)d_in[s + 8];
    const float* wk      = (const float*)d_in[s + 9];
    const float* wv      = (const float*)d_in[s + 10];
    const float* wo      = (const float*)d_in[s + 11];
    const float* bo      = (const float*)d_in[s + 12];
    const float* ln_g    = (const float*)d_in[s + 13];
    const float* ln_b    = (const float*)d_in[s + 14];
    const float* td_w    = (const float*)d_in[s + 15];
    const float* td_b    = (const float*)d_in[s + 16];
    const float* bn_g    = (const float*)d_in[s + 17];
    const float* bn_b    = (const float*)d_in[s + 18];
    const float* bn_mean = (const float*)d_in[s + 19];
    const float* bn_var  = (const float*)d_in[s + 20];

    float *h1, *h2, *hpos, *hgeo, *qb, *kb, *vb, *sb, *pre, *fb, *g512, *wt;
    cudaGetSymbolAddress((void**)&h1,   d_h1);
    cudaGetSymbolAddress((void**)&h2,   d_h2);
    cudaGetSymbolAddress((void**)&hpos, d_hpos);
    cudaGetSymbolAddress((void**)&hgeo, d_hgeo);
    cudaGetSymbolAddress((void**)&qb,   d_q);
    cudaGetSymbolAddress((void**)&kb,   d_k);
    cudaGetSymbolAddress((void**)&vb,   d_v);
    cudaGetSymbolAddress((void**)&sb,   d_s);
    cudaGetSymbolAddress((void**)&pre,  d_pre);
    cudaGetSymbolAddress((void**)&fb,   d_f);
    cudaGetSymbolAddress((void**)&g512, d_g512);
    cudaGetSymbolAddress((void**)&wt,   d_wt);

    cudaFuncSetAttribute(tc_gemm,
                         cudaFuncAttributeMaxDynamicSharedMemorySize, TC_SMEM_TOTAL);
    cudaFuncSetAttribute(attn_kernel<16>,
                         cudaFuncAttributeMaxDynamicSharedMemorySize, ATTN_SMEM);
    cudaFuncSetAttribute(attn_kernel<64>,
                         cudaFuncAttributeMaxDynamicSharedMemorySize, ATTN_SMEM);

    transpose_all<<<dim3(8, 8, 14), 256>>>(mlp1_w2, mlp2_w2, wq, wk, wv, wo, td_w, wt);

    const dim3 gemmBlk(256);
    const dim3 grid256x2(2, RTOT / 128, 2);  // batched hpos+hgeo
    const dim3 grid256(2, RTOT / 128, 1);
    const dim3 grid512(4, RTOT / 128, 1);

    for (int blk = 0; blk < 2; blk++) {
        const int cs = (blk == 0) ? 16 : 64;
        const int i  = blk;
        const float* fin = (blk == 0) ? feat : fb;
        const size_t bOff = (size_t)i * 256;
        float* Wt0 = wt + (size_t)(i * 6) * SLOT;

        geom_hidden_kernel<<<RTOT / cs, 256>>>(
            pos, mlp1_w1 + (size_t)i * 4 * 256, mlp1_b1 + bOff,
            mlp2_w1 + (size_t)i * 6 * 256, mlp2_b1 + bOff, h1, h2, cs);

        // batched: z=0: hpos = h1@W0 + b + fin ; z=1: hgeo = h2@W1 + b + fin
        tc_gemm<<<grid256x2, gemmBlk, TC_SMEM_TOTAL>>>(h1, Wt0 + 0 * SLOT, mlp1_b2 + bOff, fin,
            hpos, nullptr, DIM, 0, 1.f, nullptr, nullptr, nullptr, nullptr,
            h2, Wt0 + 1 * SLOT, mlp2_b2 + bOff, hgeo);
        // q|k fused 512-wide (separate launch; z-batching QKV regressed end-to-end)
        tc_gemm<<<grid512, gemmBlk, TC_SMEM_TOTAL>>>(hgeo, Wt0 + 2 * SLOT, nullptr, feat,
            qb, kb, DOUT, 4, 1.f / 16.f, nullptr, nullptr, nullptr, nullptr,
            nullptr, nullptr, nullptr, nullptr);
        tc_gemm<<<grid256, gemmBlk, TC_SMEM_TOTAL>>>(hpos, Wt0 + 4 * SLOT, nullptr, feat,
            vb, nullptr, DIM, 2, 1.f, nullptr, nullptr, nullptr, nullptr,
            nullptr, nullptr, nullptr, nullptr);

        if (cs == 16)
            attn_kernel<16><<<RTOT / 64, 256, ATTN_SMEM>>>(qb, kb, vb, sb);
        else
            attn_kernel<64><<<RTOT / 64, 256, ATTN_SMEM>>>(qb, kb, vb, sb);

        // pre = hpos + attn@wo + bo
        tc_gemm<<<grid256, gemmBlk, TC_SMEM_TOTAL>>>(sb, Wt0 + 5 * SLOT, bo + bOff, hpos,
            pre, nullptr, DIM, 0, 1.f, nullptr, nullptr, nullptr, nullptr,
            nullptr, nullptr, nullptr, nullptr);

        ln_kernel<<<RTOT / 8, 256>>>(pre, ln_g + bOff, ln_b + bOff, fb);
    }

    tc_gemm<<<grid512, gemmBlk, TC_SMEM_TOTAL>>>(fb, wt + 12 * SLOT, td_b, feat,
        g512, nullptr, DOUT, 3, 1.f, bn_g, bn_b, bn_mean, bn_var,
        nullptr, nullptr, nullptr, nullptr);

    float* outp = (float*)d_out;
    knn_max_kernel<<<BATCH * MPTS, 128>>>(g512, knn, pos, fps,
                                          outp, outp + BATCH * MPTS * 3);
}

// round 15
// speedup vs baseline: 1.5005x; 1.3682x over previous
#include <cuda_runtime.h>
#include <cuda_bf16.h>
#include <math.h>
#include <stdint.h>

// Problem constants
#define BATCH 8
#define NPTS  8192
#define DIM   256
#define DOUT  512
#define MPTS  2048
#define KNN   16
#define RTOT  (BATCH * NPTS)   // 65536 rows
#define EPS   1e-5f

// ---------------------------------------------------------------------------
// Scratch
// ---------------------------------------------------------------------------
__device__ __align__(128) float d_h1  [(size_t)RTOT * DIM];
__device__ __align__(128) float d_h2  [(size_t)RTOT * DIM];
__device__ __align__(128) float d_hpos[(size_t)RTOT * DIM];
__device__ __align__(128) float d_hgeo[(size_t)RTOT * DIM];
__device__ __align__(128) float d_q   [(size_t)RTOT * DIM];
__device__ __align__(128) float d_k   [(size_t)RTOT * DIM];
__device__ __align__(128) float d_v   [(size_t)RTOT * DIM];   // holds vT (chunked [t][j])
__device__ __align__(128) float d_s   [(size_t)RTOT * DIM];
__device__ __align__(128) float d_pre [(size_t)RTOT * DIM];
__device__ __align__(128) float d_f   [(size_t)RTOT * DIM];
__device__ __align__(128) float d_g512[(size_t)RTOT * DOUT];
__device__ __align__(128) float d_wt  [14 * 256 * 256];

#define SLOT (256 * 256)

// ---------------------------------------------------------------------------
// helpers
// ---------------------------------------------------------------------------
__device__ __forceinline__ float f2tf32_rn(float v) {
    uint32_t u;
    asm("cvt.rna.tf32.f32 %0, %1;" : "=r"(u) : "f"(v));
    return __uint_as_float(u);
}

__device__ __forceinline__ void mma_tf32(float* c, const uint32_t* a, const uint32_t* b) {
    asm volatile(
        "mma.sync.aligned.m16n8k8.row.col.f32.tf32.tf32.f32 "
        "{%0,%1,%2,%3}, {%4,%5,%6,%7}, {%8,%9}, {%0,%1,%2,%3};"
        : "+f"(c[0]), "+f"(c[1]), "+f"(c[2]), "+f"(c[3])
        : "r"(a[0]), "r"(a[1]), "r"(a[2]), "r"(a[3]), "r"(b[0]), "r"(b[1]));
}

__device__ __forceinline__ uint32_t smem_u32(const void* p) {
    uint32_t a;
    asm("{ .reg .u64 t; cvta.to.shared.u64 t, %1; cvt.u32.u64 %0, t; }" : "=r"(a) : "l"(p));
    return a;
}

#define CP_ASYNC16(dst, src) \
    asm volatile("cp.async.cg.shared.global [%0], [%1], 16;" :: "r"(dst), "l"(src))
#define CP_COMMIT() asm volatile("cp.async.commit_group;")
template<int N> __device__ __forceinline__ void cp_wait() {
    asm volatile("cp.async.wait_group %0;" :: "n"(N));
}

#define LDSM_X4(r, addr) \
    asm volatile("ldmatrix.sync.aligned.m8n8.x4.shared.b16 {%0,%1,%2,%3}, [%4];" \
        : "=r"((r)[0]), "=r"((r)[1]), "=r"((r)[2]), "=r"((r)[3]) : "r"(addr))
#define LDSM_X2(r, addr) \
    asm volatile("ldmatrix.sync.aligned.m8n8.x2.shared.b16 {%0,%1}, [%2];" \
        : "=r"((r)[0]), "=r"((r)[1]) : "r"(addr))

// ---------------------------------------------------------------------------
// Batched weight transpose (rounded to tf32-rn at write)
// ---------------------------------------------------------------------------
__global__ __launch_bounds__(256) void transpose_all(
    const float* __restrict__ m1w2, const float* __restrict__ m2w2,
    const float* __restrict__ wq, const float* __restrict__ wk,
    const float* __restrict__ wv, const float* __restrict__ wo,
    const float* __restrict__ td, float* __restrict__ wt)
{
    __shared__ float t[32][33];
    const int z = blockIdx.z;
    const float* src;
    int srcN = 256, colOff = 0;
    float* dst;
    if (z < 12) {
        const int i = z / 6, j = z % 6;
        const size_t off = (size_t)i * SLOT;
        switch (j) {
            case 0: src = m1w2 + off; break;
            case 1: src = m2w2 + off; break;
            case 2: src = wq   + off; break;
            case 3: src = wk   + off; break;
            case 4: src = wv   + off; break;
            default: src = wo  + off; break;
        }
        dst = wt + (size_t)(i * 6 + j) * SLOT;
    } else {
        src = td; srcN = 512; colOff = (z - 12) * 256;
        dst = wt + (size_t)(12 + (z - 12)) * SLOT;
    }

    const int bx = blockIdx.x * 32;
    const int by = blockIdx.y * 32;
    const int tx = threadIdx.x & 31, ty = threadIdx.x >> 5;
#pragma unroll
    for (int i = ty; i < 32; i += 8)
        t[i][tx] = src[(size_t)(by + i) * srcN + colOff + bx + tx];
    __syncthreads();
#pragma unroll
    for (int i = ty; i < 32; i += 8)
        dst[(size_t)(bx + i) * 256 + by + tx] = f2tf32_rn(t[tx][i]);
}

// ---------------------------------------------------------------------------
// tf32 mma.sync GEMM, cp.async + ldmatrix.
// CTA tile 128x128, 256 threads (8 warps, 2x4), warp tile 64x32.
// blockIdx.z==1 switches to job 2 (A2/W2/bias2/Cb), same mode/Nout.
// modes: 0 = +bias+Add  1 = *scale  2 = none  3 = relu(bn(acc+bias))
//        4 = dual q/k (tf32-rn)  5 = vT chunked [t][j] store (tf32-rn)
// ---------------------------------------------------------------------------
#define STG_BYTES 32768
#define TC_SMEM_TOTAL (3 * STG_BYTES)   // 96KB

__global__ void __launch_bounds__(256, 2) tc_gemm(
    const float* __restrict__ A, const float* __restrict__ Wt,
    const float* __restrict__ bias, const float* __restrict__ Add,
    float* __restrict__ C, float* __restrict__ C2,
    int Nout, int mode, float scale,
    const float* __restrict__ bn_g, const float* __restrict__ bn_b,
    const float* __restrict__ bn_mean, const float* __restrict__ bn_var,
    const float* __restrict__ A2, const float* __restrict__ W2,
    const float* __restrict__ bias2, float* __restrict__ Cb)
{
    extern __shared__ char smem[];
    const uint32_t sbase = smem_u32(smem);
    const int tid  = threadIdx.x;
    const int lane = tid & 31;
    const int wid  = tid >> 5;
    const int wr   = wid >> 2;
    const int wc   = wid & 3;

    if (blockIdx.z == 1) {
        A = A2; Wt = W2; bias = bias2; C = Cb;
    }

    const int blockRow = blockIdx.y * 128;
    const int blockCol = blockIdx.x * 128;

    const float* Abase = A  + (size_t)blockRow * 256;
    const float* Bbase = Wt + (size_t)blockCol * 256;

    int rowL[4], qL[4];
    uint32_t offL[4];
#pragma unroll
    for (int i = 0; i < 4; i++) {
        const int idx = tid + i * 256;
        rowL[i] = idx >> 3;
        qL[i]   = idx & 7;
        offL[i] = (uint32_t)rowL[i] * 128u + (uint32_t)((qL[i] ^ (rowL[i] & 7)) * 16);
    }

    auto issue_chunk = [&](int c, int s) {
        const int k0 = c * 32;
        const uint32_t ab = sbase + (uint32_t)s * STG_BYTES;
        const uint32_t bb = ab + 16384u;
#pragma unroll
        for (int i = 0; i < 4; i++)
            CP_ASYNC16(ab + offL[i], Abase + (size_t)rowL[i] * 256 + k0 + qL[i] * 4);
#pragma unroll
        for (int i = 0; i < 4; i++)
            CP_ASYNC16(bb + offL[i], Bbase + (size_t)rowL[i] * 256 + k0 + qL[i] * 4);
        CP_COMMIT();
    };

    const int l7  = lane & 7;
    const int hA  = lane >> 4;
    const int hB  = (lane >> 3) & 1;
    uint32_t aOff[4], bOff[4];
#pragma unroll
    for (int t = 0; t < 4; t++) {
        const int rA = wr * 64 + t * 16 + ((lane >> 3) & 1) * 8 + l7;
        aOff[t] = (uint32_t)rA * 128u;
        const int rB = wc * 32 + t * 8 + l7;
        bOff[t] = (uint32_t)rB * 128u;
    }

    float acc[4][4][4];
#pragma unroll
    for (int i = 0; i < 4; i++)
#pragma unroll
        for (int j = 0; j < 4; j++)
#pragma unroll
            for (int e = 0; e < 4; e++) acc[i][j][e] = 0.f;

    auto compute = [&](int s) {
        const uint32_t sA = sbase + (uint32_t)s * STG_BYTES;
        const uint32_t sB = sA + 16384u;
#pragma unroll
        for (int kt = 0; kt < 4; kt++) {
            const uint32_t qa = (uint32_t)((((kt << 1) + hA) ^ l7) << 4);
            const uint32_t qb = (uint32_t)((((kt << 1) + hB) ^ l7) << 4);
            uint32_t aF[4][4], bF[4][2];
#pragma unroll
            for (int rt4 = 0; rt4 < 4; rt4++)
                LDSM_X4(aF[rt4], sA + aOff[rt4] + qa);
#pragma unroll
            for (int nt4 = 0; nt4 < 4; nt4++)
                LDSM_X2(bF[nt4], sB + bOff[nt4] + qb);
#pragma unroll
            for (int rt4 = 0; rt4 < 4; rt4++)
#pragma unroll
                for (int nt4 = 0; nt4 < 4; nt4++)
                    mma_tf32(acc[rt4][nt4], aF[rt4], bF[nt4]);
        }
    };

    issue_chunk(0, 0);
    issue_chunk(1, 1);
#pragma unroll
    for (int c = 0; c < 8; c++) {
        if (c == 7) cp_wait<0>(); else cp_wait<1>();
        __syncthreads();
        if (c + 2 < 8) issue_chunk(c + 2, (c + 2) % 3);
        compute(c % 3);
    }

    const int g   = lane >> 2;
    const int tig = lane & 3;
#pragma unroll
    for (int rt4 = 0; rt4 < 4; rt4++) {
#pragma unroll
        for (int half = 0; half < 2; half++) {
            const int row = blockRow + wr * 64 + rt4 * 16 + g + half * 8;
            float* Crow = C + (size_t)row * Nout;
            const float* Arow = Add + (size_t)row * Nout;
#pragma unroll
            for (int nt4 = 0; nt4 < 4; nt4++) {
                const int col = blockCol + wc * 32 + nt4 * 8 + tig * 2;
                float v0 = acc[rt4][nt4][half * 2 + 0];
                float v1 = acc[rt4][nt4][half * 2 + 1];
                float2 out;
                if (mode == 0) {
                    out.x = v0 + bias[col]     + Arow[col];
                    out.y = v1 + bias[col + 1] + Arow[col + 1];
                    *(float2*)(Crow + col) = out;
                } else if (mode == 1) {
                    out.x = v0 * scale; out.y = v1 * scale;
                    *(float2*)(Crow + col) = out;
                } else if (mode == 2) {
                    out.x = v0; out.y = v1;
                    *(float2*)(Crow + col) = out;
                } else if (mode == 3) {
                    float t0 = (v0 + bias[col] - bn_mean[col]) *
                               rsqrtf(bn_var[col] + EPS) * bn_g[col] + bn_b[col];
                    float t1 = (v1 + bias[col + 1] - bn_mean[col + 1]) *
                               rsqrtf(bn_var[col + 1] + EPS) * bn_g[col + 1] + bn_b[col + 1];
                    out.x = fmaxf(t0, 0.f); out.y = fmaxf(t1, 0.f);
                    *(float2*)(Crow + col) = out;
                } else if (mode == 4) {  // dual q/k, tf32-rn
                    if (col < 256) {
                        out.x = f2tf32_rn(v0 * scale); out.y = f2tf32_rn(v1 * scale);
                        *(float2*)(C + (size_t)row * 256 + col) = out;
                    } else {
                        out.x = f2tf32_rn(v0); out.y = f2tf32_rn(v1);
                        *(float2*)(C2 + (size_t)row * 256 + (col - 256)) = out;
                    }
                } else {  // mode 5: vT chunked store: vT[chunk][t=col][j=row&63]
                    float* vt = C + (size_t)(row >> 6) * 16384 + (row & 63);
                    vt[(size_t)col * 64]       = f2tf32_rn(v0);
                    vt[(size_t)(col + 1) * 64] = f2tf32_rn(v1);
                }
            }
        }
    }
}

// ---------------------------------------------------------------------------
// Per-chunk geometry + first MLP layers
// ---------------------------------------------------------------------------
__global__ __launch_bounds__(256) void geom_hidden_kernel(
    const float* __restrict__ pos,
    const float* __restrict__ w1, const float* __restrict__ b1,
    const float* __restrict__ w2, const float* __restrict__ b2,
    float* __restrict__ H1, float* __restrict__ H2, int cs)
{
    __shared__ float ps[64][3];
    __shared__ float lp[64][4];
    __shared__ float cog[3], avg[3];

    const int tid = threadIdx.x;
    const size_t gp = (size_t)blockIdx.x * cs;

    if (tid < cs) {
        ps[tid][0] = pos[(gp + tid) * 3 + 0];
        ps[tid][1] = pos[(gp + tid) * 3 + 1];
        ps[tid][2] = pos[(gp + tid) * 3 + 2];
    }
    __syncthreads();
    if (tid < 3) {
        float s = 0.f;
        for (int p = 0; p < cs; p++) s += ps[p][tid];
        cog[tid] = s / (float)cs;
    }
    __syncthreads();
    if (tid < cs) {
        float x = ps[tid][0] - cog[0];
        float y = ps[tid][1] - cog[1];
        float z = ps[tid][2] - cog[2];
        lp[tid][0] = x; lp[tid][1] = y; lp[tid][2] = z;
        lp[tid][3] = sqrtf(x * x + y * y + z * z);
    }
    __syncthreads();
    if (tid < 3) {
        float s = 0.f;
        for (int p = 0; p < cs; p++) s += lp[p][tid];
        avg[tid] = s / (float)cs;
    }
    __syncthreads();

    const int j = tid;
    float w1c[4], w2c[6];
#pragma unroll
    for (int t = 0; t < 4; t++) w1c[t] = w1[t * 256 + j];
#pragma unroll
    for (int t = 0; t < 6; t++) w2c[t] = w2[t * 256 + j];
    const float b1v = b1[j], b2v = b2[j];
    const float a0 = avg[0], a1 = avg[1], a2 = avg[2];

    for (int p = 0; p < cs; p++) {
        float x = lp[p][0], y = lp[p][1], z = lp[p][2], n = lp[p][3];
        float h1 = fmaxf(b1v + x * w1c[0] + y * w1c[1] + z * w1c[2] + n * w1c[3], 0.f);
        float h2 = fmaxf(b2v + a0 * w2c[0] + a1 * w2c[1] + a2 * w2c[2] +
                               x * w2c[3] + y * w2c[4] + z * w2c[5], 0.f);
        H1[(gp + p) * 256 + j] = f2tf32_rn(h1);
        H2[(gp + p) * 256 + j] = f2tf32_rn(h2);
    }
}

// ---------------------------------------------------------------------------
// Tensor-core attention. CTA = 64 points.
// smem: Q [0,64K) + K [64K,128K) in GEMM layout; P at 128K (64 x stride-68 f32);
// Vt (2 j-chunks x 256 t-rows, GEMM layout) overlays [0,64K) after QK.
// ---------------------------------------------------------------------------
#define PSTRIDE 68
#define ATTN_SMEM (131072 + 64 * PSTRIDE * 4)   // 148480

template<int CS>
__global__ __launch_bounds__(256, 1) void attn_mma(
    const float* __restrict__ Q, const float* __restrict__ Kf,
    const float* __restrict__ VT, float* __restrict__ Out)
{
    extern __shared__ char smem[];
    const uint32_t sbase = smem_u32(smem);
    float* P = (float*)(smem + 131072);
    const int tid  = threadIdx.x;
    const int lane = tid & 31;
    const int wid  = tid >> 5;
    const int l7   = lane & 7;
    const int hA   = lane >> 4;
    const int hB   = (lane >> 3) & 1;
    const int g    = lane >> 2;
    const int tig  = lane & 3;

    const size_t base = (size_t)blockIdx.x * 64 * 256;

    // ---- load Q,K (8 chunks of 32 k-floats, 64 rows each) ----
    {
        int rowL[2], qL[2];
        uint32_t offL[2];
#pragma unroll
        for (int i = 0; i < 2; i++) {
            const int idx = tid + i * 256;
            rowL[i] = idx >> 3;          // 0..63
            qL[i]   = idx & 7;
            offL[i] = (uint32_t)rowL[i] * 128u + (uint32_t)((qL[i] ^ (rowL[i] & 7)) * 16);
        }
#pragma unroll
        for (int c = 0; c < 8; c++) {
            const uint32_t cb = (uint32_t)c * 8192u;
#pragma unroll
            for (int i = 0; i < 2; i++) {
                CP_ASYNC16(sbase + cb + offL[i],
                           Q  + base + (size_t)rowL[i] * 256 + c * 32 + qL[i] * 4);
                CP_ASYNC16(sbase + 65536u + cb + offL[i],
                           Kf + base + (size_t)rowL[i] * 256 + c * 32 + qL[i] * 4);
            }
        }
        CP_COMMIT();
        cp_wait<0>();
        __syncthreads();
    }

    // ---- QK^T via mma: warps 4x2, warp tile 16x32 ----
    {
        const int wr4 = wid >> 1;        // 0..3 -> 16-row tile
        const int wc2 = wid & 1;         // 0..1 -> 32-col slab
        const uint32_t aOff = (uint32_t)(wr4 * 16 + hB * 8 + l7) * 128u;
        uint32_t bOff[4];
#pragma unroll
        for (int nt = 0; nt < 4; nt++)
            bOff[nt] = 65536u + (uint32_t)(wc2 * 32 + nt * 8 + l7) * 128u;

        float acc[4][4];
#pragma unroll
        for (int i = 0; i < 4; i++)
#pragma unroll
            for (int e = 0; e < 4; e++) acc[i][e] = 0.f;

#pragma unroll
        for (int c = 0; c < 8; c++) {
            const uint32_t cb = (uint32_t)c * 8192u;
#pragma unroll
            for (int kt = 0; kt < 4; kt++) {
                const uint32_t qa = (uint32_t)((((kt << 1) + hA) ^ l7) << 4);
                const uint32_t qb = (uint32_t)((((kt << 1) + hB) ^ l7) << 4);
                uint32_t aF[4], bF[4][2];
                LDSM_X4(aF, sbase + cb + aOff + qa);
#pragma unroll
                for (int nt = 0; nt < 4; nt++)
                    LDSM_X2(bF[nt], sbase + cb + bOff[nt] + qb);
#pragma unroll
                for (int nt = 0; nt < 4; nt++)
                    mma_tf32(acc[nt], aF, bF[nt]);
            }
        }
        // write logits
#pragma unroll
        for (int nt = 0; nt < 4; nt++)
#pragma unroll
            for (int half = 0; half < 2; half++) {
                const int r  = wr4 * 16 + g + half * 8;
                const int cc = wc2 * 32 + nt * 8 + tig * 2;
                float2 o; o.x = acc[nt][half * 2]; o.y = acc[nt][half * 2 + 1];
                *(float2*)&P[r * PSTRIDE + cc] = o;
            }
    }
    __syncthreads();

    // ---- phase 2: Vt cp.async (all threads) + softmax (subset) ----
    {
        int rowV[8], qV[8];
        uint32_t offV[8];
#pragma unroll
        for (int i = 0; i < 8; i++) {
            const int idx = tid + i * 256;       // over 2048 f4 per chunk
            rowV[i] = idx >> 3;                  // 0..255 (t)
            qV[i]   = idx & 7;
            offV[i] = (uint32_t)rowV[i] * 128u + (uint32_t)((qV[i] ^ (rowV[i] & 7)) * 16);
        }
        const float* vtg = VT + (size_t)blockIdx.x * 16384;
#pragma unroll
        for (int cj = 0; cj < 2; cj++) {
#pragma unroll
            for (int i = 0; i < 8; i++)
                CP_ASYNC16(sbase + (uint32_t)cj * 32768u + offV[i],
                           vtg + (size_t)rowV[i] * 64 + cj * 32 + qV[i] * 4);
        }
        CP_COMMIT();

        if (CS == 64) {
            for (int i = wid; i < 64; i += 8) {
                float* row = P + i * PSTRIDE;
                float a = row[lane], b = row[lane + 32];
                float mx = fmaxf(a, b);
#pragma unroll
                for (int o = 16; o; o >>= 1) mx = fmaxf(mx, __shfl_xor_sync(0xFFFFFFFFu, mx, o));
                float ea = __expf(a - mx), eb = __expf(b - mx);
                float sum = ea + eb;
#pragma unroll
                for (int o = 16; o; o >>= 1) sum += __shfl_xor_sync(0xFFFFFFFFu, sum, o);
                float inv = 1.f / sum;
                row[lane]      = f2tf32_rn(ea * inv);
                row[lane + 32] = f2tf32_rn(eb * inv);
            }
        } else {
            if (tid < 64) {
                const int r  = tid;
                const int cb = r & ~15;
                float* row = P + r * PSTRIDE;
                float mx = -1e30f;
#pragma unroll
                for (int j = 0; j < 16; j++) mx = fmaxf(mx, row[cb + j]);
                float e[16];
                float sum = 0.f;
#pragma unroll
                for (int j = 0; j < 16; j++) { e[j] = __expf(row[cb + j] - mx); sum += e[j]; }
                const float inv = 1.f / sum;
                // zero cross-chunk cols, write probs in-chunk
                for (int j = 0; j < 64; j++) row[j] = 0.f;
#pragma unroll
                for (int j = 0; j < 16; j++) row[cb + j] = f2tf32_rn(e[j] * inv);
            }
        }
        cp_wait<0>();
        __syncthreads();
    }

    // ---- SV via mma: warps 2x4, warp tile 32x64. A = P (plain units), B = Vt ----
    {
        const int wrS = wid >> 2;        // 0..1 -> 32-row slab
        const int wcS = wid & 3;         // 0..3 -> 64-col slab
        uint32_t aOffS[2];
#pragma unroll
        for (int t16 = 0; t16 < 2; t16++)
            aOffS[t16] = 131072u + (uint32_t)(wrS * 32 + t16 * 16 + hB * 8 + l7) * (PSTRIDE * 4);
        uint32_t bOffS[8];
#pragma unroll
        for (int nt = 0; nt < 8; nt++)
            bOffS[nt] = (uint32_t)(wcS * 64 + nt * 8 + l7) * 128u;

        float acc[2][8][4];
#pragma unroll
        for (int i = 0; i < 2; i++)
#pragma unroll
            for (int j = 0; j < 8; j++)
#pragma unroll
                for (int e = 0; e < 4; e++) acc[i][j][e] = 0.f;

#pragma unroll
        for (int kt = 0; kt < 8; kt++) {
            const int cj  = kt >> 2;
            const int ktc = kt & 3;
            const uint32_t qa = (uint32_t)(((kt << 1) + hA) << 4);             // plain units
            const uint32_t qb = (uint32_t)((((ktc << 1) + hB) ^ l7) << 4);      // swizzled
            uint32_t aF[2][4], bF[8][2];
#pragma unroll
            for (int t16 = 0; t16 < 2; t16++)
                LDSM_X4(aF[t16], sbase + aOffS[t16] + qa);
#pragma unroll
            for (int nt = 0; nt < 8; nt++)
                LDSM_X2(bF[nt], sbase + (uint32_t)cj * 32768u + bOffS[nt] + qb);
#pragma unroll
            for (int t16 = 0; t16 < 2; t16++)
#pragma unroll
                for (int nt = 0; nt < 8; nt++)
                    mma_tf32(acc[t16][nt], aF[t16], bF[nt]);
        }

#pragma unroll
        for (int t16 = 0; t16 < 2; t16++)
#pragma unroll
            for (int half = 0; half < 2; half++) {
                const int r = wrS * 32 + t16 * 16 + g + half * 8;
                float* Orow = Out + base + (size_t)r * 256;
#pragma unroll
                for (int nt = 0; nt < 8; nt++) {
                    const int cc = wcS * 64 + nt * 8 + tig * 2;
                    float2 o;
                    o.x = f2tf32_rn(acc[t16][nt][half * 2 + 0]);
                    o.y = f2tf32_rn(acc[t16][nt][half * 2 + 1]);
                    *(float2*)&Orow[cc] = o;
                }
            }
    }
}

// ---------------------------------------------------------------------------
// LayerNorm: warp-per-row, 8 rows per CTA.
// ---------------------------------------------------------------------------
__global__ __launch_bounds__(256) void ln_kernel(
    const float* __restrict__ X, const float* __restrict__ g,
    const float* __restrict__ b, float* __restrict__ Y)
{
    const int warp = threadIdx.x >> 5, lane = threadIdx.x & 31;
    const size_t row = (size_t)blockIdx.x * 8 + warp;
    const float4* xr = (const float4*)(X + row * 256);
    float4 x0 = xr[lane], x1 = xr[lane + 32];

    float s = x0.x + x0.y + x0.z + x0.w + x1.x + x1.y + x1.z + x1.w;
#pragma unroll
    for (int o = 16; o; o >>= 1) s += __shfl_xor_sync(0xFFFFFFFFu, s, o);
    const float mu = s * (1.f / 256.f);

    float v = 0.f;
    float d0x = x0.x - mu, d0y = x0.y - mu, d0z = x0.z - mu, d0w = x0.w - mu;
    float d1x = x1.x - mu, d1y = x1.y - mu, d1z = x1.z - mu, d1w = x1.w - mu;
    v = d0x*d0x + d0y*d0y + d0z*d0z + d0w*d0w + d1x*d1x + d1y*d1y + d1z*d1z + d1w*d1w;
#pragma unroll
    for (int o = 16; o; o >>= 1) v += __shfl_xor_sync(0xFFFFFFFFu, v, o);
    const float inv = rsqrtf(v * (1.f / 256.f) + EPS);

    const float4 g0 = *(const float4*)&g[lane * 4];
    const float4 g1 = *(const float4*)&g[(lane + 32) * 4];
    const float4 b0 = *(const float4*)&b[lane * 4];
    const float4 b1 = *(const float4*)&b[(lane + 32) * 4];
    float4 y0, y1;
    y0.x = d0x * inv * g0.x + b0.x; y0.y = d0y * inv * g0.y + b0.y;
    y0.z = d0z * inv * g0.z + b0.z; y0.w = d0w * inv * g0.w + b0.w;
    y1.x = d1x * inv * g1.x + b1.x; y1.y = d1y * inv * g1.y + b1.y;
    y1.z = d1z * inv * g1.z + b1.z; y1.w = d1w * inv * g1.w + b1.w;
    float4* yr = (float4*)(Y + row * 256);
    yr[lane] = y0; yr[lane + 32] = y1;
}

// ---------------------------------------------------------------------------
// kNN gather + channel max (float4) + fused pos downsample
// ---------------------------------------------------------------------------
__global__ __launch_bounds__(128) void knn_max_kernel(
    const float* __restrict__ G, const int* __restrict__ knn,
    const float* __restrict__ pos, const int* __restrict__ fps,
    float* __restrict__ outPos, float* __restrict__ outFeat)
{
    const int bm = blockIdx.x;
    const int b  = bm / MPTS;
    const int tid = threadIdx.x;
    __shared__ int idxs[KNN];
    if (tid < KNN) idxs[tid] = knn[(size_t)bm * KNN + tid];
    if (tid >= 32 && tid < 35) {
        const int c = tid - 32;
        outPos[bm * 3 + c] = pos[((size_t)b * NPTS + fps[bm]) * 3 + c];
    }
    __syncthreads();
    float4 m = make_float4(-3.0e38f, -3.0e38f, -3.0e38f, -3.0e38f);
#pragma unroll
    for (int k = 0; k < KNN; k++) {
        const float4 gg = *(const float4*)&G[((size_t)b * NPTS + idxs[k]) * DOUT + tid * 4];
        m.x = fmaxf(m.x, gg.x); m.y = fmaxf(m.y, gg.y);
        m.z = fmaxf(m.z, gg.z); m.w = fmaxf(m.w, gg.w);
    }
    *(float4*)&outFeat[(size_t)bm * DOUT + tid * 4] = m;
}

// ---------------------------------------------------------------------------
// Orchestration
// ---------------------------------------------------------------------------
extern "C" void kernel_launch(void* const* d_in, const int* in_sizes, int n_in,
                              void* d_out, int out_size)
{
    const int s = (n_in >= 27) ? 6 : 4;

    const float* pos     = (const float*)d_in[0];
    const float* feat    = (const float*)d_in[1];
    const int*   fps     = (const int*)  d_in[2];
    const int*   knn     = (const int*)  d_in[3];
    const float* mlp1_w1 = (const float*)d_in[s + 0];
    const float* mlp1_b1 = (const float*)d_in[s + 1];
    const float* mlp1_w2 = (const float*)d_in[s + 2];
    const float* mlp1_b2 = (const float*)d_in[s + 3];
    const float* mlp2_w1 = (const float*)d_in[s + 4];
    const float* mlp2_b1 = (const float*)d_in[s + 5];
    const float* mlp2_w2 = (const float*)d_in[s + 6];
    const float* mlp2_b2 = (const float*)d_in[s + 7];
    const float* wq      = (const float*)d_in[s + 8];
    const float* wk      = (const float*)d_in[s + 9];
    const float* wv      = (const float*)d_in[s + 10];
    const float* wo      = (const float*)d_in[s + 11];
    const float* bo      = (const float*)d_in[s + 12];
    const float* ln_g    = (const float*)d_in[s + 13];
    const float* ln_b    = (const float*)d_in[s + 14];
    const float* td_w    = (const float*)d_in[s + 15];
    const float* td_b    = (const float*)d_in[s + 16];
    const float* bn_g    = (const float*)d_in[s + 17];
    const float* bn_b    = (const float*)d_in[s + 18];
    const float* bn_mean = (const float*)d_in[s + 19];
    const float* bn_var  = (const float*)d_in[s + 20];

    float *h1, *h2, *hpos, *hgeo, *qb, *kb, *vb, *sb, *pre, *fb, *g512, *wt;
    cudaGetSymbolAddress((void**)&h1,   d_h1);
    cudaGetSymbolAddress((void**)&h2,   d_h2);
    cudaGetSymbolAddress((void**)&hpos, d_hpos);
    cudaGetSymbolAddress((void**)&hgeo, d_hgeo);
    cudaGetSymbolAddress((void**)&qb,   d_q);
    cudaGetSymbolAddress((void**)&kb,   d_k);
    cudaGetSymbolAddress((void**)&vb,   d_v);
    cudaGetSymbolAddress((void**)&sb,   d_s);
    cudaGetSymbolAddress((void**)&pre,  d_pre);
    cudaGetSymbolAddress((void**)&fb,   d_f);
    cudaGetSymbolAddress((void**)&g512, d_g512);
    cudaGetSymbolAddress((void**)&wt,   d_wt);

    cudaFuncSetAttribute(tc_gemm,
                         cudaFuncAttributeMaxDynamicSharedMemorySize, TC_SMEM_TOTAL);
    cudaFuncSetAttribute(attn_mma<16>,
                         cudaFuncAttributeMaxDynamicSharedMemorySize, ATTN_SMEM);
    cudaFuncSetAttribute(attn_mma<64>,
                         cudaFuncAttributeMaxDynamicSharedMemorySize, ATTN_SMEM);

    transpose_all<<<dim3(8, 8, 14), 256>>>(mlp1_w2, mlp2_w2, wq, wk, wv, wo, td_w, wt);

    const dim3 gemmBlk(256);
    const dim3 grid256x2(2, RTOT / 128, 2);  // batched hpos+hgeo
    const dim3 grid256(2, RTOT / 128, 1);
    const dim3 grid512(4, RTOT / 128, 1);

    for (int blk = 0; blk < 2; blk++) {
        const int cs = (blk == 0) ? 16 : 64;
        const int i  = blk;
        const float* fin = (blk == 0) ? feat : fb;
        const size_t bOff = (size_t)i * 256;
        float* Wt0 = wt + (size_t)(i * 6) * SLOT;

        geom_hidden_kernel<<<RTOT / cs, 256>>>(
            pos, mlp1_w1 + (size_t)i * 4 * 256, mlp1_b1 + bOff,
            mlp2_w1 + (size_t)i * 6 * 256, mlp2_b1 + bOff, h1, h2, cs);

        tc_gemm<<<grid256x2, gemmBlk, TC_SMEM_TOTAL>>>(h1, Wt0 + 0 * SLOT, mlp1_b2 + bOff, fin,
            hpos, nullptr, DIM, 0, 1.f, nullptr, nullptr, nullptr, nullptr,
            h2, Wt0 + 1 * SLOT, mlp2_b2 + bOff, hgeo);
        tc_gemm<<<grid512, gemmBlk, TC_SMEM_TOTAL>>>(hgeo, Wt0 + 2 * SLOT, nullptr, feat,
            qb, kb, DOUT, 4, 1.f / 16.f, nullptr, nullptr, nullptr, nullptr,
            nullptr, nullptr, nullptr, nullptr);
        // v in chunked-transposed layout (mode 5)
        tc_gemm<<<grid256, gemmBlk, TC_SMEM_TOTAL>>>(hpos, Wt0 + 4 * SLOT, nullptr, feat,
            vb, nullptr, DIM, 5, 1.f, nullptr, nullptr, nullptr, nullptr,
            nullptr, nullptr, nullptr, nullptr);

        if (cs == 16)
            attn_mma<16><<<RTOT / 64, 256, ATTN_SMEM>>>(qb, kb, vb, sb);
        else
            attn_mma<64><<<RTOT / 64, 256, ATTN_SMEM>>>(qb, kb, vb, sb);

        tc_gemm<<<grid256, gemmBlk, TC_SMEM_TOTAL>>>(sb, Wt0 + 5 * SLOT, bo + bOff, hpos,
            pre, nullptr, DIM, 0, 1.f, nullptr, nullptr, nullptr, nullptr,
            nullptr, nullptr, nullptr, nullptr);

        ln_kernel<<<RTOT / 8, 256>>>(pre, ln_g + bOff, ln_b + bOff, fb);
    }

    tc_gemm<<<grid512, gemmBlk, TC_SMEM_TOTAL>>>(fb, wt + 12 * SLOT, td_b, feat,
        g512, nullptr, DOUT, 3, 1.f, bn_g, bn_b, bn_mean, bn_var,
        nullptr, nullptr, nullptr, nullptr);

    float* outp = (float*)d_out;
    knn_max_kernel<<<BATCH * MPTS, 128>>>(g512, knn, pos, fps,
                                          outp, outp + BATCH * MPTS * 3);
}

// round 17
// speedup vs baseline: 1.5295x; 1.0194x over previous
#include <cuda_runtime.h>
#include <cuda_bf16.h>
#include <math.h>
#include <stdint.h>

// Problem constants
#define BATCH 8
#define NPTS  8192
#define DIM   256
#define DOUT  512
#define MPTS  2048
#define KNN   16
#define RTOT  (BATCH * NPTS)   // 65536 rows
#define EPS   1e-5f

// ---------------------------------------------------------------------------
// Scratch
// ---------------------------------------------------------------------------
__device__ __align__(128) float d_h1  [(size_t)RTOT * DIM];
__device__ __align__(128) float d_h2  [(size_t)RTOT * DIM];
__device__ __align__(128) float d_hpos[(size_t)RTOT * DIM];
__device__ __align__(128) float d_hgeo[(size_t)RTOT * DIM];
__device__ __align__(128) float d_q   [(size_t)RTOT * DIM];
__device__ __align__(128) float d_k   [(size_t)RTOT * DIM];
__device__ __align__(128) float d_s   [(size_t)RTOT * DIM];
__device__ __align__(128) float d_pre [(size_t)RTOT * DIM];
__device__ __align__(128) float d_f   [(size_t)RTOT * DIM];
__device__ __align__(128) float d_g512[(size_t)RTOT * DOUT];
__device__ __align__(128) float d_wt  [14 * 256 * 256];

#define SLOT (256 * 256)

// ---------------------------------------------------------------------------
// helpers
// ---------------------------------------------------------------------------
__device__ __forceinline__ float f2tf32_rn(float v) {
    uint32_t u;
    asm("cvt.rna.tf32.f32 %0, %1;" : "=r"(u) : "f"(v));
    return __uint_as_float(u);
}

__device__ __forceinline__ void mma_tf32(float* c, const uint32_t* a, const uint32_t* b) {
    asm volatile(
        "mma.sync.aligned.m16n8k8.row.col.f32.tf32.tf32.f32 "
        "{%0,%1,%2,%3}, {%4,%5,%6,%7}, {%8,%9}, {%0,%1,%2,%3};"
        : "+f"(c[0]), "+f"(c[1]), "+f"(c[2]), "+f"(c[3])
        : "r"(a[0]), "r"(a[1]), "r"(a[2]), "r"(a[3]), "r"(b[0]), "r"(b[1]));
}

__device__ __forceinline__ uint32_t smem_u32(const void* p) {
    uint32_t a;
    asm("{ .reg .u64 t; cvta.to.shared.u64 t, %1; cvt.u32.u64 %0, t; }" : "=r"(a) : "l"(p));
    return a;
}

#define CP_ASYNC16(dst, src) \
    asm volatile("cp.async.cg.shared.global [%0], [%1], 16;" :: "r"(dst), "l"(src))
#define CP_COMMIT() asm volatile("cp.async.commit_group;")
template<int N> __device__ __forceinline__ void cp_wait() {
    asm volatile("cp.async.wait_group %0;" :: "n"(N));
}

#define LDSM_X4(r, addr) \
    asm volatile("ldmatrix.sync.aligned.m8n8.x4.shared.b16 {%0,%1,%2,%3}, [%4];" \
        : "=r"((r)[0]), "=r"((r)[1]), "=r"((r)[2]), "=r"((r)[3]) : "r"(addr))
#define LDSM_X2(r, addr) \
    asm volatile("ldmatrix.sync.aligned.m8n8.x2.shared.b16 {%0,%1}, [%2];" \
        : "=r"((r)[0]), "=r"((r)[1]) : "r"(addr))

// ---------------------------------------------------------------------------
// Batched weight transpose (rounded to tf32-rn at write)
// ---------------------------------------------------------------------------
__global__ __launch_bounds__(256) void transpose_all(
    const float* __restrict__ m1w2, const float* __restrict__ m2w2,
    const float* __restrict__ wq, const float* __restrict__ wk,
    const float* __restrict__ wv, const float* __restrict__ wo,
    const float* __restrict__ td, float* __restrict__ wt)
{
    __shared__ float t[32][33];
    const int z = blockIdx.z;
    const float* src;
    int srcN = 256, colOff = 0;
    float* dst;
    if (z < 12) {
        const int i = z / 6, j = z % 6;
        const size_t off = (size_t)i * SLOT;
        switch (j) {
            case 0: src = m1w2 + off; break;
            case 1: src = m2w2 + off; break;
            case 2: src = wq   + off; break;
            case 3: src = wk   + off; break;
            case 4: src = wv   + off; break;
            default: src = wo  + off; break;
        }
        dst = wt + (size_t)(i * 6 + j) * SLOT;
    } else {
        src = td; srcN = 512; colOff = (z - 12) * 256;
        dst = wt + (size_t)(12 + (z - 12)) * SLOT;
    }

    const int bx = blockIdx.x * 32;
    const int by = blockIdx.y * 32;
    const int tx = threadIdx.x & 31, ty = threadIdx.x >> 5;
#pragma unroll
    for (int i = ty; i < 32; i += 8)
        t[i][tx] = src[(size_t)(by + i) * srcN + colOff + bx + tx];
    __syncthreads();
#pragma unroll
    for (int i = ty; i < 32; i += 8)
        dst[(size_t)(bx + i) * 256 + by + tx] = f2tf32_rn(t[tx][i]);
}

// ---------------------------------------------------------------------------
// tf32 mma.sync GEMM, cp.async + ldmatrix. 128x128, 256 thr, 3-stage, 2 CTA/SM.
// blockIdx.z==1 switches to job 2 (A2/W2/bias2/Cb), same mode/Nout.
// modes: 0 = +bias+Add  1 = *scale  2 = none  3 = relu(bn(acc+bias))
//        4 = dual q/k (tf32-rn)
// ---------------------------------------------------------------------------
#define STG_BYTES 32768
#define TC_SMEM_TOTAL (3 * STG_BYTES)   // 96KB

__global__ void __launch_bounds__(256, 2) tc_gemm(
    const float* __restrict__ A, const float* __restrict__ Wt,
    const float* __restrict__ bias, const float* __restrict__ Add,
    float* __restrict__ C, float* __restrict__ C2,
    int Nout, int mode, float scale,
    const float* __restrict__ bn_g, const float* __restrict__ bn_b,
    const float* __restrict__ bn_mean, const float* __restrict__ bn_var,
    const float* __restrict__ A2, const float* __restrict__ W2,
    const float* __restrict__ bias2, float* __restrict__ Cb)
{
    extern __shared__ char smem[];
    const uint32_t sbase = smem_u32(smem);
    const int tid  = threadIdx.x;
    const int lane = tid & 31;
    const int wid  = tid >> 5;
    const int wr   = wid >> 2;
    const int wc   = wid & 3;

    if (blockIdx.z == 1) {
        A = A2; Wt = W2; bias = bias2; C = Cb;
    }

    const int blockRow = blockIdx.y * 128;
    const int blockCol = blockIdx.x * 128;

    const float* Abase = A  + (size_t)blockRow * 256;
    const float* Bbase = Wt + (size_t)blockCol * 256;

    int rowL[4], qL[4];
    uint32_t offL[4];
#pragma unroll
    for (int i = 0; i < 4; i++) {
        const int idx = tid + i * 256;
        rowL[i] = idx >> 3;
        qL[i]   = idx & 7;
        offL[i] = (uint32_t)rowL[i] * 128u + (uint32_t)((qL[i] ^ (rowL[i] & 7)) * 16);
    }

    auto issue_chunk = [&](int c, int s) {
        const int k0 = c * 32;
        const uint32_t ab = sbase + (uint32_t)s * STG_BYTES;
        const uint32_t bb = ab + 16384u;
#pragma unroll
        for (int i = 0; i < 4; i++)
            CP_ASYNC16(ab + offL[i], Abase + (size_t)rowL[i] * 256 + k0 + qL[i] * 4);
#pragma unroll
        for (int i = 0; i < 4; i++)
            CP_ASYNC16(bb + offL[i], Bbase + (size_t)rowL[i] * 256 + k0 + qL[i] * 4);
        CP_COMMIT();
    };

    const int l7  = lane & 7;
    const int hA  = lane >> 4;
    const int hB  = (lane >> 3) & 1;
    uint32_t aOff[4], bOff[4];
#pragma unroll
    for (int t = 0; t < 4; t++) {
        const int rA = wr * 64 + t * 16 + ((lane >> 3) & 1) * 8 + l7;
        aOff[t] = (uint32_t)rA * 128u;
        const int rB = wc * 32 + t * 8 + l7;
        bOff[t] = (uint32_t)rB * 128u;
    }

    float acc[4][4][4];
#pragma unroll
    for (int i = 0; i < 4; i++)
#pragma unroll
        for (int j = 0; j < 4; j++)
#pragma unroll
            for (int e = 0; e < 4; e++) acc[i][j][e] = 0.f;

    auto compute = [&](int s) {
        const uint32_t sA = sbase + (uint32_t)s * STG_BYTES;
        const uint32_t sB = sA + 16384u;
#pragma unroll
        for (int kt = 0; kt < 4; kt++) {
            const uint32_t qa = (uint32_t)((((kt << 1) + hA) ^ l7) << 4);
            const uint32_t qb = (uint32_t)((((kt << 1) + hB) ^ l7) << 4);
            uint32_t aF[4][4], bF[4][2];
#pragma unroll
            for (int rt4 = 0; rt4 < 4; rt4++)
                LDSM_X4(aF[rt4], sA + aOff[rt4] + qa);
#pragma unroll
            for (int nt4 = 0; nt4 < 4; nt4++)
                LDSM_X2(bF[nt4], sB + bOff[nt4] + qb);
#pragma unroll
            for (int rt4 = 0; rt4 < 4; rt4++)
#pragma unroll
                for (int nt4 = 0; nt4 < 4; nt4++)
                    mma_tf32(acc[rt4][nt4], aF[rt4], bF[nt4]);
        }
    };

    issue_chunk(0, 0);
    issue_chunk(1, 1);
#pragma unroll
    for (int c = 0; c < 8; c++) {
        if (c == 7) cp_wait<0>(); else cp_wait<1>();
        __syncthreads();
        if (c + 2 < 8) issue_chunk(c + 2, (c + 2) % 3);
        compute(c % 3);
    }

    const int g   = lane >> 2;
    const int tig = lane & 3;
#pragma unroll
    for (int rt4 = 0; rt4 < 4; rt4++) {
#pragma unroll
        for (int half = 0; half < 2; half++) {
            const int row = blockRow + wr * 64 + rt4 * 16 + g + half * 8;
            float* Crow = C + (size_t)row * Nout;
            const float* Arow = Add + (size_t)row * Nout;
#pragma unroll
            for (int nt4 = 0; nt4 < 4; nt4++) {
                const int col = blockCol + wc * 32 + nt4 * 8 + tig * 2;
                float v0 = acc[rt4][nt4][half * 2 + 0];
                float v1 = acc[rt4][nt4][half * 2 + 1];
                float2 out;
                if (mode == 0) {
                    out.x = v0 + bias[col]     + Arow[col];
                    out.y = v1 + bias[col + 1] + Arow[col + 1];
                    *(float2*)(Crow + col) = out;
                } else if (mode == 1) {
                    out.x = v0 * scale; out.y = v1 * scale;
                    *(float2*)(Crow + col) = out;
                } else if (mode == 2) {
                    out.x = v0; out.y = v1;
                    *(float2*)(Crow + col) = out;
                } else if (mode == 3) {
                    float t0 = (v0 + bias[col] - bn_mean[col]) *
                               rsqrtf(bn_var[col] + EPS) * bn_g[col] + bn_b[col];
                    float t1 = (v1 + bias[col + 1] - bn_mean[col + 1]) *
                               rsqrtf(bn_var[col + 1] + EPS) * bn_g[col + 1] + bn_b[col + 1];
                    out.x = fmaxf(t0, 0.f); out.y = fmaxf(t1, 0.f);
                    *(float2*)(Crow + col) = out;
                } else {  // mode 4: dual q/k, tf32-rn
                    if (col < 256) {
                        out.x = f2tf32_rn(v0 * scale); out.y = f2tf32_rn(v1 * scale);
                        *(float2*)(C + (size_t)row * 256 + col) = out;
                    } else {
                        out.x = f2tf32_rn(v0); out.y = f2tf32_rn(v1);
                        *(float2*)(C2 + (size_t)row * 256 + (col - 256)) = out;
                    }
                }
            }
        }
    }
}

// ---------------------------------------------------------------------------
// Per-chunk geometry + first MLP layers
// ---------------------------------------------------------------------------
__global__ __launch_bounds__(256) void geom_hidden_kernel(
    const float* __restrict__ pos,
    const float* __restrict__ w1, const float* __restrict__ b1,
    const float* __restrict__ w2, const float* __restrict__ b2,
    float* __restrict__ H1, float* __restrict__ H2, int cs)
{
    __shared__ float ps[64][3];
    __shared__ float lp[64][4];
    __shared__ float cog[3], avg[3];

    const int tid = threadIdx.x;
    const size_t gp = (size_t)blockIdx.x * cs;

    if (tid < cs) {
        ps[tid][0] = pos[(gp + tid) * 3 + 0];
        ps[tid][1] = pos[(gp + tid) * 3 + 1];
        ps[tid][2] = pos[(gp + tid) * 3 + 2];
    }
    __syncthreads();
    if (tid < 3) {
        float s = 0.f;
        for (int p = 0; p < cs; p++) s += ps[p][tid];
        cog[tid] = s / (float)cs;
    }
    __syncthreads();
    if (tid < cs) {
        float x = ps[tid][0] - cog[0];
        float y = ps[tid][1] - cog[1];
        float z = ps[tid][2] - cog[2];
        lp[tid][0] = x; lp[tid][1] = y; lp[tid][2] = z;
        lp[tid][3] = sqrtf(x * x + y * y + z * z);
    }
    __syncthreads();
    if (tid < 3) {
        float s = 0.f;
        for (int p = 0; p < cs; p++) s += lp[p][tid];
        avg[tid] = s / (float)cs;
    }
    __syncthreads();

    const int j = tid;
    float w1c[4], w2c[6];
#pragma unroll
    for (int t = 0; t < 4; t++) w1c[t] = w1[t * 256 + j];
#pragma unroll
    for (int t = 0; t < 6; t++) w2c[t] = w2[t * 256 + j];
    const float b1v = b1[j], b2v = b2[j];
    const float a0 = avg[0], a1 = avg[1], a2 = avg[2];

    for (int p = 0; p < cs; p++) {
        float x = lp[p][0], y = lp[p][1], z = lp[p][2], n = lp[p][3];
        float h1 = fmaxf(b1v + x * w1c[0] + y * w1c[1] + z * w1c[2] + n * w1c[3], 0.f);
        float h2 = fmaxf(b2v + a0 * w2c[0] + a1 * w2c[1] + a2 * w2c[2] +
                               x * w2c[3] + y * w2c[4] + z * w2c[5], 0.f);
        H1[(gp + p) * 256 + j] = f2tf32_rn(h1);
        H2[(gp + p) * 256 + j] = f2tf32_rn(h2);
    }
}

// ---------------------------------------------------------------------------
// Tensor-core attention with fused V generation. CTA = 64 points.
// smem map:
//   [0,      65536)  Q (GEMM layout, 8 chunks)   -> later Vt (2 j-chunks x 32KB)
//   [65536, 188416)  K (QK phase) / 3-stage v-gen ring (40960 ea: A 8K + B 32K)
//   [188416,205824)  P (64 rows x stride-68 f32)
// ---------------------------------------------------------------------------
#define PSTRIDE    68
#define ATTN_PB    188416u
#define ATTN_STG   65536u
#define ATTN_SMEM  205824

template<int CS>
__global__ __launch_bounds__(256, 1) void attn_mma(
    const float* __restrict__ Q, const float* __restrict__ Kf,
    const float* __restrict__ HP, const float* __restrict__ WV,
    float* __restrict__ Out)
{
    extern __shared__ char smem[];
    const uint32_t sbase = smem_u32(smem);
    float* P = (float*)(smem + ATTN_PB);
    const int tid  = threadIdx.x;
    const int lane = tid & 31;
    const int wid  = tid >> 5;
    const int l7   = lane & 7;
    const int hA   = lane >> 4;
    const int hB   = (lane >> 3) & 1;
    const int g    = lane >> 2;
    const int tig  = lane & 3;

    const size_t base = (size_t)blockIdx.x * 64 * 256;

    // ---- load Q,K ----
    {
        int rowL[2], qL[2];
        uint32_t offL[2];
#pragma unroll
        for (int i = 0; i < 2; i++) {
            const int idx = tid + i * 256;
            rowL[i] = idx >> 3;
            qL[i]   = idx & 7;
            offL[i] = (uint32_t)rowL[i] * 128u + (uint32_t)((qL[i] ^ (rowL[i] & 7)) * 16);
        }
#pragma unroll
        for (int c = 0; c < 8; c++) {
            const uint32_t cb = (uint32_t)c * 8192u;
#pragma unroll
            for (int i = 0; i < 2; i++) {
                CP_ASYNC16(sbase + cb + offL[i],
                           Q  + base + (size_t)rowL[i] * 256 + c * 32 + qL[i] * 4);
                CP_ASYNC16(sbase + 65536u + cb + offL[i],
                           Kf + base + (size_t)rowL[i] * 256 + c * 32 + qL[i] * 4);
            }
        }
        CP_COMMIT();
        cp_wait<0>();
        __syncthreads();
    }

    // ---- QK^T via mma: warps 4x2, warp tile 16x32 ----
    {
        const int wr4 = wid >> 1;
        const int wc2 = wid & 1;
        const uint32_t aOff = (uint32_t)(wr4 * 16 + hB * 8 + l7) * 128u;
        uint32_t bOff[4];
#pragma unroll
        for (int nt = 0; nt < 4; nt++)
            bOff[nt] = 65536u + (uint32_t)(wc2 * 32 + nt * 8 + l7) * 128u;

        float acc[4][4];
#pragma unroll
        for (int i = 0; i < 4; i++)
#pragma unroll
            for (int e = 0; e < 4; e++) acc[i][e] = 0.f;

#pragma unroll
        for (int c = 0; c < 8; c++) {
            const uint32_t cb = (uint32_t)c * 8192u;
#pragma unroll
            for (int kt = 0; kt < 4; kt++) {
                const uint32_t qa = (uint32_t)((((kt << 1) + hA) ^ l7) << 4);
                const uint32_t qb = (uint32_t)((((kt << 1) + hB) ^ l7) << 4);
                uint32_t aF[4], bF[4][2];
                LDSM_X4(aF, sbase + cb + aOff + qa);
#pragma unroll
                for (int nt = 0; nt < 4; nt++)
                    LDSM_X2(bF[nt], sbase + cb + bOff[nt] + qb);
#pragma unroll
                for (int nt = 0; nt < 4; nt++)
                    mma_tf32(acc[nt], aF, bF[nt]);
            }
        }
#pragma unroll
        for (int nt = 0; nt < 4; nt++)
#pragma unroll
            for (int half = 0; half < 2; half++) {
                const int r  = wr4 * 16 + g + half * 8;
                const int cc = wc2 * 32 + nt * 8 + tig * 2;
                float2 o; o.x = acc[nt][half * 2]; o.y = acc[nt][half * 2 + 1];
                *(float2*)&P[r * PSTRIDE + cc] = o;
            }
    }
    __syncthreads();

    // ---- fused V generation + softmax ----
    {
        // loaders: A (hpos chunk) 512 f4 -> 2/thread; B (wvT) 2048 f4 -> 8/thread
        int rowA[2], qA2[2]; uint32_t offA2[2];
#pragma unroll
        for (int i = 0; i < 2; i++) {
            const int idx = tid + i * 256;
            rowA[i] = idx >> 3; qA2[i] = idx & 7;
            offA2[i] = (uint32_t)rowA[i] * 128u + (uint32_t)((qA2[i] ^ (rowA[i] & 7)) * 16);
        }
        int rowB[8], qB8[8]; uint32_t offB8[8];
#pragma unroll
        for (int i = 0; i < 8; i++) {
            const int idx = tid + i * 256;
            rowB[i] = idx >> 3; qB8[i] = idx & 7;
            offB8[i] = (uint32_t)rowB[i] * 128u + (uint32_t)((qB8[i] ^ (rowB[i] & 7)) * 16);
        }

        auto issue_v = [&](int kc, int s) {
            const uint32_t ab = sbase + ATTN_STG + (uint32_t)s * 40960u;
            const uint32_t bb = ab + 8192u;
#pragma unroll
            for (int i = 0; i < 2; i++)
                CP_ASYNC16(ab + offA2[i], HP + base + (size_t)rowA[i] * 256 + kc * 32 + qA2[i] * 4);
#pragma unroll
            for (int i = 0; i < 8; i++)
                CP_ASYNC16(bb + offB8[i], WV + (size_t)rowB[i] * 256 + kc * 32 + qB8[i] * 4);
            CP_COMMIT();
        };

        issue_v(0, 0);
        issue_v(1, 1);

        // softmax on P (overlaps the first V loads)
        if (CS == 64) {
            for (int i = wid; i < 64; i += 8) {
                float* row = P + i * PSTRIDE;
                float a = row[lane], b = row[lane + 32];
                float mx = fmaxf(a, b);
#pragma unroll
                for (int o = 16; o; o >>= 1) mx = fmaxf(mx, __shfl_xor_sync(0xFFFFFFFFu, mx, o));
                float ea = __expf(a - mx), eb = __expf(b - mx);
                float sum = ea + eb;
#pragma unroll
                for (int o = 16; o; o >>= 1) sum += __shfl_xor_sync(0xFFFFFFFFu, sum, o);
                float inv = 1.f / sum;
                row[lane]      = f2tf32_rn(ea * inv);
                row[lane + 32] = f2tf32_rn(eb * inv);
            }
        } else {
            if (tid < 64) {
                const int r  = tid;
                const int cb = r & ~15;
                float* row = P + r * PSTRIDE;
                float mx = -1e30f;
#pragma unroll
                for (int j = 0; j < 16; j++) mx = fmaxf(mx, row[cb + j]);
                float e[16];
                float sum = 0.f;
#pragma unroll
                for (int j = 0; j < 16; j++) { e[j] = __expf(row[cb + j] - mx); sum += e[j]; }
                const float inv = 1.f / sum;
                for (int j = 0; j < 64; j++) row[j] = 0.f;
#pragma unroll
                for (int j = 0; j < 16; j++) row[cb + j] = f2tf32_rn(e[j] * inv);
            }
        }

        // V accumulation: warps 2x4, warp tile 32x64 (rows j, cols t)
        const int wrV = wid >> 2;
        const int wcV = wid & 3;
        uint32_t aOffV[2], bOffV[8];
#pragma unroll
        for (int t16 = 0; t16 < 2; t16++)
            aOffV[t16] = (uint32_t)(wrV * 32 + t16 * 16 + hB * 8 + l7) * 128u;
#pragma unroll
        for (int nt = 0; nt < 8; nt++)
            bOffV[nt] = (uint32_t)(wcV * 64 + nt * 8 + l7) * 128u;

        float accV[2][8][4];
#pragma unroll
        for (int i = 0; i < 2; i++)
#pragma unroll
            for (int j = 0; j < 8; j++)
#pragma unroll
                for (int e = 0; e < 4; e++) accV[i][j][e] = 0.f;

#pragma unroll
        for (int kc = 0; kc < 8; kc++) {
            if (kc == 7) cp_wait<0>(); else cp_wait<1>();
            __syncthreads();
            if (kc + 2 < 8) issue_v(kc + 2, (kc + 2) % 3);
            const uint32_t sA = sbase + ATTN_STG + (uint32_t)(kc % 3) * 40960u;
            const uint32_t sB = sA + 8192u;
#pragma unroll
            for (int kt = 0; kt < 4; kt++) {
                const uint32_t qa = (uint32_t)((((kt << 1) + hA) ^ l7) << 4);
                const uint32_t qb = (uint32_t)((((kt << 1) + hB) ^ l7) << 4);
                uint32_t aF[2][4], bF[8][2];
#pragma unroll
                for (int t16 = 0; t16 < 2; t16++)
                    LDSM_X4(aF[t16], sA + aOffV[t16] + qa);
#pragma unroll
                for (int nt = 0; nt < 8; nt++)
                    LDSM_X2(bF[nt], sB + bOffV[nt] + qb);
#pragma unroll
                for (int t16 = 0; t16 < 2; t16++)
#pragma unroll
                    for (int nt = 0; nt < 8; nt++)
                        mma_tf32(accV[t16][nt], aF[t16], bF[nt]);
            }
        }
        __syncthreads();

        // scatter vT into [0,64K): chunk cj = j>>5, row t, elem jj = j&31
#pragma unroll
        for (int t16 = 0; t16 < 2; t16++) {
#pragma unroll
            for (int half = 0; half < 2; half++) {
                const int j  = wrV * 32 + t16 * 16 + g + half * 8;
                const uint32_t cjb = (uint32_t)(j >> 5) * 32768u;
                const int jj = j & 31;
                const uint32_t u = (uint32_t)(jj >> 2);
                const uint32_t eb = (uint32_t)(jj & 3) * 4u;
#pragma unroll
                for (int nt = 0; nt < 8; nt++) {
                    const int t0 = wcV * 64 + nt * 8 + tig * 2;
                    *(float*)(smem + cjb + (uint32_t)t0 * 128u +
                              ((u ^ (uint32_t)(t0 & 7)) << 4) + eb) =
                        f2tf32_rn(accV[t16][nt][half * 2 + 0]);
                    *(float*)(smem + cjb + (uint32_t)(t0 + 1) * 128u +
                              ((u ^ (uint32_t)((t0 + 1) & 7)) << 4) + eb) =
                        f2tf32_rn(accV[t16][nt][half * 2 + 1]);
                }
            }
        }
        __syncthreads();
    }

    // ---- SV via mma: warps 2x4, warp tile 32x64. A = P (plain), B = Vt smem ----
    {
        const int wrS = wid >> 2;
        const int wcS = wid & 3;
        uint32_t aOffS[2];
#pragma unroll
        for (int t16 = 0; t16 < 2; t16++)
            aOffS[t16] = ATTN_PB + (uint32_t)(wrS * 32 + t16 * 16 + hB * 8 + l7) * (PSTRIDE * 4);
        uint32_t bOffS[8];
#pragma unroll
        for (int nt = 0; nt < 8; nt++)
            bOffS[nt] = (uint32_t)(wcS * 64 + nt * 8 + l7) * 128u;

        float acc[2][8][4];
#pragma unroll
        for (int i = 0; i < 2; i++)
#pragma unroll
            for (int j = 0; j < 8; j++)
#pragma unroll
                for (int e = 0; e < 4; e++) acc[i][j][e] = 0.f;

#pragma unroll
        for (int kt = 0; kt < 8; kt++) {
            const int cj  = kt >> 2;
            const int ktc = kt & 3;
            const uint32_t qa = (uint32_t)(((kt << 1) + hA) << 4);
            const uint32_t qb = (uint32_t)((((ktc << 1) + hB) ^ l7) << 4);
            uint32_t aF[2][4], bF[8][2];
#pragma unroll
            for (int t16 = 0; t16 < 2; t16++)
                LDSM_X4(aF[t16], sbase + aOffS[t16] + qa);
#pragma unroll
            for (int nt = 0; nt < 8; nt++)
                LDSM_X2(bF[nt], sbase + (uint32_t)cj * 32768u + bOffS[nt] + qb);
#pragma unroll
            for (int t16 = 0; t16 < 2; t16++)
#pragma unroll
                for (int nt = 0; nt < 8; nt++)
                    mma_tf32(acc[t16][nt], aF[t16], bF[nt]);
        }

#pragma unroll
        for (int t16 = 0; t16 < 2; t16++)
#pragma unroll
            for (int half = 0; half < 2; half++) {
                const int r = wrS * 32 + t16 * 16 + g + half * 8;
                float* Orow = Out + base + (size_t)r * 256;
#pragma unroll
                for (int nt = 0; nt < 8; nt++) {
                    const int cc = wcS * 64 + nt * 8 + tig * 2;
                    float2 o;
                    o.x = f2tf32_rn(acc[t16][nt][half * 2 + 0]);
                    o.y = f2tf32_rn(acc[t16][nt][half * 2 + 1]);
                    *(float2*)&Orow[cc] = o;
                }
            }
    }
}

// ---------------------------------------------------------------------------
// LayerNorm: warp-per-row, 8 rows per CTA.
// ---------------------------------------------------------------------------
__global__ __launch_bounds__(256) void ln_kernel(
    const float* __restrict__ X, const float* __restrict__ g,
    const float* __restrict__ b, float* __restrict__ Y)
{
    const int warp = threadIdx.x >> 5, lane = threadIdx.x & 31;
    const size_t row = (size_t)blockIdx.x * 8 + warp;
    const float4* xr = (const float4*)(X + row * 256);
    float4 x0 = xr[lane], x1 = xr[lane + 32];

    float s = x0.x + x0.y + x0.z + x0.w + x1.x + x1.y + x1.z + x1.w;
#pragma unroll
    for (int o = 16; o; o >>= 1) s += __shfl_xor_sync(0xFFFFFFFFu, s, o);
    const float mu = s * (1.f / 256.f);

    float v = 0.f;
    float d0x = x0.x - mu, d0y = x0.y - mu, d0z = x0.z - mu, d0w = x0.w - mu;
    float d1x = x1.x - mu, d1y = x1.y - mu, d1z = x1.z - mu, d1w = x1.w - mu;
    v = d0x*d0x + d0y*d0y + d0z*d0z + d0w*d0w + d1x*d1x + d1y*d1y + d1z*d1z + d1w*d1w;
#pragma unroll
    for (int o = 16; o; o >>= 1) v += __shfl_xor_sync(0xFFFFFFFFu, v, o);
    const float inv = rsqrtf(v * (1.f / 256.f) + EPS);

    const float4 g0 = *(const float4*)&g[lane * 4];
    const float4 g1 = *(const float4*)&g[(lane + 32) * 4];
    const float4 b0 = *(const float4*)&b[lane * 4];
    const float4 b1 = *(const float4*)&b[(lane + 32) * 4];
    float4 y0, y1;
    y0.x = d0x * inv * g0.x + b0.x; y0.y = d0y * inv * g0.y + b0.y;
    y0.z = d0z * inv * g0.z + b0.z; y0.w = d0w * inv * g0.w + b0.w;
    y1.x = d1x * inv * g1.x + b1.x; y1.y = d1y * inv * g1.y + b1.y;
    y1.z = d1z * inv * g1.z + b1.z; y1.w = d1w * inv * g1.w + b1.w;
    float4* yr = (float4*)(Y + row * 256);
    yr[lane] = y0; yr[lane + 32] = y1;
}

// ---------------------------------------------------------------------------
// kNN gather + channel max (float4) + fused pos downsample
// ---------------------------------------------------------------------------
__global__ __launch_bounds__(128) void knn_max_kernel(
    const float* __restrict__ G, const int* __restrict__ knn,
    const float* __restrict__ pos, const int* __restrict__ fps,
    float* __restrict__ outPos, float* __restrict__ outFeat)
{
    const int bm = blockIdx.x;
    const int b  = bm / MPTS;
    const int tid = threadIdx.x;
    __shared__ int idxs[KNN];
    if (tid < KNN) idxs[tid] = knn[(size_t)bm * KNN + tid];
    if (tid >= 32 && tid < 35) {
        const int c = tid - 32;
        outPos[bm * 3 + c] = pos[((size_t)b * NPTS + fps[bm]) * 3 + c];
    }
    __syncthreads();
    float4 m = make_float4(-3.0e38f, -3.0e38f, -3.0e38f, -3.0e38f);
#pragma unroll
    for (int k = 0; k < KNN; k++) {
        const float4 gg = *(const float4*)&G[((size_t)b * NPTS + idxs[k]) * DOUT + tid * 4];
        m.x = fmaxf(m.x, gg.x); m.y = fmaxf(m.y, gg.y);
        m.z = fmaxf(m.z, gg.z); m.w = fmaxf(m.w, gg.w);
    }
    *(float4*)&outFeat[(size_t)bm * DOUT + tid * 4] = m;
}

// ---------------------------------------------------------------------------
// Orchestration
// ---------------------------------------------------------------------------
extern "C" void kernel_launch(void* const* d_in, const int* in_sizes, int n_in,
                              void* d_out, int out_size)
{
    const int s = (n_in >= 27) ? 6 : 4;

    const float* pos     = (const float*)d_in[0];
    const float* feat    = (const float*)d_in[1];
    const int*   fps     = (const int*)  d_in[2];
    const int*   knn     = (const int*)  d_in[3];
    const float* mlp1_w1 = (const float*)d_in[s + 0];
    const float* mlp1_b1 = (const float*)d_in[s + 1];
    const float* mlp1_w2 = (const float*)d_in[s + 2];
    const float* mlp1_b2 = (const float*)d_in[s + 3];
    const float* mlp2_w1 = (const float*)d_in[s + 4];
    const float* mlp2_b1 = (const float*)d_in[s + 5];
    const float* mlp2_w2 = (const float*)d_in[s + 6];
    const float* mlp2_b2 = (const float*)d_in[s + 7];
    const float* wq      = (const float*)d_in[s + 8];
    const float* wk      = (const float*)d_in[s + 9];
    const float* wv      = (const float*)d_in[s + 10];
    const float* wo      = (const float*)d_in[s + 11];
    const float* bo      = (const float*)d_in[s + 12];
    const float* ln_g    = (const float*)d_in[s + 13];
    const float* ln_b    = (const float*)d_in[s + 14];
    const float* td_w    = (const float*)d_in[s + 15];
    const float* td_b    = (const float*)d_in[s + 16];
    const float* bn_g    = (const float*)d_in[s + 17];
    const float* bn_b    = (const float*)d_in[s + 18];
    const float* bn_mean = (const float*)d_in[s + 19];
    const float* bn_var  = (const float*)d_in[s + 20];

    float *h1, *h2, *hpos, *hgeo, *qb, *kb, *sb, *pre, *fb, *g512, *wt;
    cudaGetSymbolAddress((void**)&h1,   d_h1);
    cudaGetSymbolAddress((void**)&h2,   d_h2);
    cudaGetSymbolAddress((void**)&hpos, d_hpos);
    cudaGetSymbolAddress((void**)&hgeo, d_hgeo);
    cudaGetSymbolAddress((void**)&qb,   d_q);
    cudaGetSymbolAddress((void**)&kb,   d_k);
    cudaGetSymbolAddress((void**)&sb,   d_s);
    cudaGetSymbolAddress((void**)&pre,  d_pre);
    cudaGetSymbolAddress((void**)&fb,   d_f);
    cudaGetSymbolAddress((void**)&g512, d_g512);
    cudaGetSymbolAddress((void**)&wt,   d_wt);

    cudaFuncSetAttribute(tc_gemm,
                         cudaFuncAttributeMaxDynamicSharedMemorySize, TC_SMEM_TOTAL);
    cudaFuncSetAttribute(attn_mma<16>,
                         cudaFuncAttributeMaxDynamicSharedMemorySize, ATTN_SMEM);
    cudaFuncSetAttribute(attn_mma<64>,
                         cudaFuncAttributeMaxDynamicSharedMemorySize, ATTN_SMEM);

    transpose_all<<<dim3(8, 8, 14), 256>>>(mlp1_w2, mlp2_w2, wq, wk, wv, wo, td_w, wt);

    const dim3 gemmBlk(256);
    const dim3 grid256x2(2, RTOT / 128, 2);  // batched hpos+hgeo
    const dim3 grid256(2, RTOT / 128, 1);
    const dim3 grid512(4, RTOT / 128, 1);

    for (int blk = 0; blk < 2; blk++) {
        const int cs = (blk == 0) ? 16 : 64;
        const int i  = blk;
        const float* fin = (blk == 0) ? feat : fb;
        const size_t bOff = (size_t)i * 256;
        float* Wt0 = wt + (size_t)(i * 6) * SLOT;

        geom_hidden_kernel<<<RTOT / cs, 256>>>(
            pos, mlp1_w1 + (size_t)i * 4 * 256, mlp1_b1 + bOff,
            mlp2_w1 + (size_t)i * 6 * 256, mlp2_b1 + bOff, h1, h2, cs);

        tc_gemm<<<grid256x2, gemmBlk, TC_SMEM_TOTAL>>>(h1, Wt0 + 0 * SLOT, mlp1_b2 + bOff, fin,
            hpos, nullptr, DIM, 0, 1.f, nullptr, nullptr, nullptr, nullptr,
            h2, Wt0 + 1 * SLOT, mlp2_b2 + bOff, hgeo);
        tc_gemm<<<grid512, gemmBlk, TC_SMEM_TOTAL>>>(hgeo, Wt0 + 2 * SLOT, nullptr, feat,
            qb, kb, DOUT, 4, 1.f / 16.f, nullptr, nullptr, nullptr, nullptr,
            nullptr, nullptr, nullptr, nullptr);

        // attention with fused V generation (v = hpos @ wv computed in-kernel)
        if (cs == 16)
            attn_mma<16><<<RTOT / 64, 256, ATTN_SMEM>>>(qb, kb, hpos, Wt0 + 4 * SLOT, sb);
        else
            attn_mma<64><<<RTOT / 64, 256, ATTN_SMEM>>>(qb, kb, hpos, Wt0 + 4 * SLOT, sb);

        tc_gemm<<<grid256, gemmBlk, TC_SMEM_TOTAL>>>(sb, Wt0 + 5 * SLOT, bo + bOff, hpos,
            pre, nullptr, DIM, 0, 1.f, nullptr, nullptr, nullptr, nullptr,
            nullptr, nullptr, nullptr, nullptr);

        ln_kernel<<<RTOT / 8, 256>>>(pre, ln_g + bOff, ln_b + bOff, fb);
    }

    tc_gemm<<<grid512, gemmBlk, TC_SMEM_TOTAL>>>(fb, wt + 12 * SLOT, td_b, feat,
        g512, nullptr, DOUT, 3, 1.f, bn_g, bn_b, bn_mean, bn_var,
        nullptr, nullptr, nullptr, nullptr);

    float* outp = (float*)d_out;
    knn_max_kernel<<<BATCH * MPTS, 128>>>(g512, knn, pos, fps,
                                          outp, outp + BATCH * MPTS * 3);
}